// round 3
// baseline (speedup 1.0000x reference)
#include <cuda_runtime.h>
#include <math.h>

// ---------------- problem constants ----------------
constexpr int kB    = 16;    // batch
constexpr int kL    = 64;    // sequence length (8x8 grid, snake order)
constexpr int kD    = 256;   // model dim
constexpr int kDIN  = 512;   // inner dim
constexpr int kH    = 8;     // heads
constexpr int kDH   = 64;    // head dim
constexpr int kN    = 64;    // state dim
constexpr int kCDIM = 640;   // DIN + 2*G*N
constexpr int kP    = 1160;  // in_proj width (2*DIN + 2*G*N + H)
constexpr int kPF   = 768;   // patch features 3*16*16
constexpr int kCLS  = 1000;
constexpr float kEPS = 1e-6f;
constexpr int kTOK  = kB * kL;  // 1024

// ---------------- scratch (device globals; no allocation allowed) ----------------
__device__ float g_patches[kTOK*kPF];
__device__ float g_pwT[kPF*kD];
__device__ float g_t[kTOK*kD];
__device__ float g_nx[kTOK*kD];
__device__ float g_zx[2][kTOK*kP];
__device__ float g_conv[2][kTOK*kCDIM];
__device__ float g_dtv[2][kTOK*kH];
__device__ float g_y[2][kTOK*kDIN];
__device__ float g_o[2][kTOK*kD];
__device__ float g_pool[kB*kD];

// ---------------- helpers ----------------
__device__ __forceinline__ int snake_src(int l) {
    int r = l >> 3, c = l & 7;
    return r * 8 + ((r & 1) ? (7 - c) : c);
}

__device__ __forceinline__ float block_reduce_sum_256(float v) {
    __shared__ float sh[8];
    __shared__ float tot;
    int lane = threadIdx.x & 31, w = threadIdx.x >> 5;
    #pragma unroll
    for (int o = 16; o > 0; o >>= 1) v += __shfl_xor_sync(0xffffffffu, v, o);
    if (lane == 0) sh[w] = v;
    __syncthreads();
    if (w == 0) {
        float x = (lane < 8) ? sh[lane] : 0.f;
        #pragma unroll
        for (int o = 4; o > 0; o >>= 1) x += __shfl_xor_sync(0xffffffffu, x, o);
        if (lane == 0) tot = x;
    }
    __syncthreads();
    return tot;
}

__device__ __forceinline__ float siluf(float x) {
    return x / (1.f + expf(-x));
}

// ---------------- kernels ----------------

// patch_w (256,768) -> pwT (768,256)
__global__ void k_transpose_pw(const float* __restrict__ w, float* __restrict__ wt) {
    int o = blockIdx.x * blockDim.x + threadIdx.x;
    if (o >= kPF * kD) return;
    int k = o / kD, n = o % kD;
    wt[o] = w[n * kPF + k];
}

// patchify into snake order
__global__ void k_patchify(const float* __restrict__ x, float* __restrict__ p) {
    int idx = blockIdx.x * blockDim.x + threadIdx.x;
    if (idx >= kTOK * kPF) return;
    int f = idx % kPF;
    int l = (idx / kPF) % kL;
    int b = idx / (kPF * kL);
    int src = snake_src(l);
    int gr = src >> 3, gc = src & 7;
    int ch = f / 256, pr = (f / 16) % 16, pc = f % 16;
    p[idx] = x[((b * 3 + ch) * 128 + gr * 16 + pr) * 128 + gc * 16 + pc];
}

// t += patch_b + pos_embed[snake(l)]
__global__ void k_addpos(float* __restrict__ t, const float* __restrict__ pb,
                         const float* __restrict__ pos) {
    int idx = blockIdx.x * blockDim.x + threadIdx.x;
    if (idx >= kTOK * kD) return;
    int d = idx % kD;
    int l = (idx / kD) % kL;
    t[idx] += pb[d] + pos[snake_src(l) * kD + d];
}

// batched SGEMM over dir (blockIdx.z): C[z] = A[z] @ B[z]
// A = Abase + z*strideA, B = z ? B1 : B0, C = Cbase + z*strideC. Row-major, K%16==0.
__global__ void k_sgemm_b(const float* __restrict__ Abase,
                          const float* __restrict__ B0, const float* __restrict__ B1,
                          float* __restrict__ Cbase,
                          int M, int N, int K, long strideA, long strideC) {
    __shared__ float As[16][65];
    __shared__ float Bs[16][65];
    int z = blockIdx.z;
    const float* A = Abase + (long)z * strideA;
    const float* B = z ? B1 : B0;
    float* C = Cbase + (long)z * strideC;
    int tid = threadIdx.x;          // 256
    int tx = tid & 15, ty = tid >> 4;
    int m0 = blockIdx.y * 64, n0 = blockIdx.x * 64;
    float acc[4][4] = {};
    for (int k0 = 0; k0 < K; k0 += 16) {
        #pragma unroll
        for (int i = 0; i < 4; i++) {
            int e = tid + i * 256;
            int r = e >> 4, cc = e & 15;
            int gm = m0 + r;
            As[cc][r] = (gm < M) ? A[gm * K + k0 + cc] : 0.f;
        }
        #pragma unroll
        for (int i = 0; i < 4; i++) {
            int e = tid + i * 256;
            int r = e >> 6, cc = e & 63;
            int gn = n0 + cc;
            Bs[r][cc] = (gn < N) ? B[(k0 + r) * N + gn] : 0.f;
        }
        __syncthreads();
        #pragma unroll
        for (int kk = 0; kk < 16; kk++) {
            float ar[4], br[4];
            #pragma unroll
            for (int j = 0; j < 4; j++) ar[j] = As[kk][ty * 4 + j];
            #pragma unroll
            for (int j = 0; j < 4; j++) br[j] = Bs[kk][tx * 4 + j];
            #pragma unroll
            for (int a = 0; a < 4; a++)
                #pragma unroll
                for (int bb = 0; bb < 4; bb++)
                    acc[a][bb] += ar[a] * br[bb];
        }
        __syncthreads();
    }
    #pragma unroll
    for (int a = 0; a < 4; a++) {
        int gm = m0 + ty * 4 + a;
        if (gm >= M) continue;
        #pragma unroll
        for (int bb = 0; bb < 4; bb++) {
            int gn = n0 + tx * 4 + bb;
            if (gn < N) C[gm * N + gn] = acc[a][bb];
        }
    }
}

// rmsnorm over 256 dims; one block per row
__global__ void k_rmsnorm256(const float* __restrict__ in, const float* __restrict__ w,
                             float* __restrict__ out) {
    int row = blockIdx.x;
    int d = threadIdx.x;
    float v = in[row * kD + d];
    float ss = block_reduce_sum_256(v * v);
    out[row * kD + d] = v * rsqrtf(ss * (1.f / kD) + kEPS) * w[d];
}

// causal depthwise conv (window 4) + silu, both dirs; scan-order output
__global__ void k_conv2(const float* __restrict__ zxbase,
                        const float* __restrict__ cw0, const float* __restrict__ cw1,
                        const float* __restrict__ cb0, const float* __restrict__ cb1,
                        float* __restrict__ outbase) {
    int idx = blockIdx.x * blockDim.x + threadIdx.x;
    if (idx >= 2 * kTOK * kCDIM) return;
    int dir = idx >= kTOK * kCDIM;
    int i = idx - dir * kTOK * kCDIM;
    const float* zx = zxbase + (long)dir * kTOK * kP;
    const float* cw = dir ? cw1 : cw0;
    const float* cb = dir ? cb1 : cb0;
    int c = i % kCDIM;
    int s = (i / kCDIM) % kL;
    int b = i / (kCDIM * kL);
    float acc = cb[c];
    #pragma unroll
    for (int k = 0; k < 4; k++) {
        int sp = s - 3 + k;
        if (sp >= 0) {
            int tok = dir ? (kL - 1 - sp) : sp;
            acc += cw[c * 4 + k] * zx[(b * kL + tok) * kP + kDIN + c];
        }
    }
    outbase[idx] = siluf(acc);
}

// dt = softplus(zx_dt + dtb), both dirs, scan order
__global__ void k_dt2(const float* __restrict__ zxbase,
                      const float* __restrict__ dtb0, const float* __restrict__ dtb1,
                      float* __restrict__ dtbase) {
    int idx = blockIdx.x * blockDim.x + threadIdx.x;
    if (idx >= 2 * kTOK * kH) return;
    int dir = idx >= kTOK * kH;
    int i = idx - dir * kTOK * kH;
    const float* zx = zxbase + (long)dir * kTOK * kP;
    const float* dtb = dir ? dtb1 : dtb0;
    int h = i % kH;
    int s = (i / kH) % kL;
    int b = i / (kH * kL);
    int tok = dir ? (kL - 1 - s) : s;
    float v = zx[(b * kL + tok) * kP + 2 * kDIN + 2 * kN + h] + dtb[h];
    dtbase[idx] = (v > 20.f) ? v : log1pf(expf(v));
}

// selective-scan, both dirs: grid (B, H, 2); 256 threads hold 64x64 state
__global__ void k_scan2(const float* __restrict__ convbase, const float* __restrict__ dtbase,
                        const float* __restrict__ Alog0, const float* __restrict__ Alog1,
                        const float* __restrict__ Dp0, const float* __restrict__ Dp1,
                        float* __restrict__ ybase) {
    int b = blockIdx.x;
    int h = blockIdx.y;
    int dir = blockIdx.z;
    const float* conv = convbase + (long)dir * kTOK * kCDIM;
    const float* dt   = dtbase   + (long)dir * kTOK * kH;
    float* y          = ybase    + (long)dir * kTOK * kDIN;
    float a = -expf((dir ? Alog1 : Alog0)[h]);
    float dpar = (dir ? Dp1 : Dp0)[h];
    int tid = threadIdx.x;          // 256
    int p = tid >> 2;
    int nb = (tid & 3) * 16;
    float hst[16];
    #pragma unroll
    for (int j = 0; j < 16; j++) hst[j] = 0.f;
    __shared__ float sX[64], sB[64], sC[64];
    __shared__ float sdt;
    for (int s = 0; s < kL; s++) {
        const float* row = conv + (b * kL + s) * kCDIM;
        if (tid < 64) sX[tid] = row[h * kDH + tid];
        else if (tid < 128) sB[tid - 64] = row[kDIN + (tid - 64)];
        else if (tid < 192) sC[tid - 128] = row[kDIN + kN + (tid - 128)];
        else if (tid == 192) sdt = dt[(b * kL + s) * kH + h];
        __syncthreads();
        float dtv = sdt;
        float decay = expf(dtv * a);
        float xv = sX[p];
        float dtx = dtv * xv;
        float acc = 0.f;
        #pragma unroll
        for (int j = 0; j < 16; j++) {
            hst[j] = decay * hst[j] + dtx * sB[nb + j];
            acc += hst[j] * sC[nb + j];
        }
        acc += __shfl_xor_sync(0xffffffffu, acc, 1);
        acc += __shfl_xor_sync(0xffffffffu, acc, 2);
        if ((tid & 3) == 0) {
            int tok = dir ? (kL - 1 - s) : s;
            y[(b * kL + tok) * kDIN + h * kDH + p] = acc + dpar * xv;
        }
        __syncthreads();
    }
}

// y = rmsnorm(y * silu(z), gn), both dirs; 2*TOK rows (zx/y contiguous across dirs)
__global__ void k_gate_norm2(const float* __restrict__ zxbase,
                             const float* __restrict__ gn0, const float* __restrict__ gn1,
                             float* __restrict__ ybase) {
    int row = blockIdx.x;           // 0..2*TOK-1
    const float* gn = (row >= kTOK) ? gn1 : gn0;
    const float* zrow = zxbase + (long)row * kP;
    float* yrow = ybase + (long)row * kDIN;
    int t = threadIdx.x;            // 256
    float v0 = yrow[t] * siluf(zrow[t]);
    float v1 = yrow[t + 256] * siluf(zrow[t + 256]);
    float ss = block_reduce_sum_256(v0 * v0 + v1 * v1);
    float sc = rsqrtf(ss * (1.f / kDIN) + kEPS);
    yrow[t]       = v0 * sc * gn[t];
    yrow[t + 256] = v1 * sc * gn[t + 256];
}

// t += 0.5*(o0 + o1)
__global__ void k_residual(float* __restrict__ t, const float* __restrict__ o0,
                           const float* __restrict__ o1) {
    int idx = blockIdx.x * blockDim.x + threadIdx.x;
    if (idx >= kTOK * kD) return;
    t[idx] += 0.5f * (o0[idx] + o1[idx]);
}

// mean over L
__global__ void k_mean(const float* __restrict__ nx, float* __restrict__ pool) {
    int idx = blockIdx.x * blockDim.x + threadIdx.x;
    if (idx >= kB * kD) return;
    int d = idx % kD, b = idx / kD;
    float s = 0.f;
    for (int l = 0; l < kL; l++) s += nx[(b * kL + l) * kD + d];
    pool[idx] = s * (1.f / kL);
}

// out = pool @ head_w + head_b
__global__ void k_head(const float* __restrict__ pool, const float* __restrict__ hw,
                       const float* __restrict__ hb, float* __restrict__ out) {
    int idx = blockIdx.x * blockDim.x + threadIdx.x;
    if (idx >= kB * kCLS) return;
    int n = idx % kCLS, b = idx / kCLS;
    float s = hb[n];
    const float* prow = pool + b * kD;
    for (int k = 0; k < kD; k++) s += prow[k] * hw[k * kCLS + n];
    out[idx] = s;
}

// ---------------- launch ----------------
extern "C" void kernel_launch(void* const* d_in, const int* in_sizes, int n_in,
                              void* d_out, int out_size) {
    const float* x       = (const float*)d_in[0];
    const float* patch_w = (const float*)d_in[1];
    const float* patch_b = (const float*)d_in[2];
    const float* pos     = (const float*)d_in[3];
    const float* norms_w = (const float*)d_in[4];
    const float* final_w = (const float*)d_in[5];
    const float* head_w  = (const float*)d_in[6];
    const float* head_b  = (const float*)d_in[7];
    const float* Win[2]  = {(const float*)d_in[8],  (const float*)d_in[16]};
    const float* cw[2]   = {(const float*)d_in[9],  (const float*)d_in[17]};
    const float* cb[2]   = {(const float*)d_in[10], (const float*)d_in[18]};
    const float* dtb[2]  = {(const float*)d_in[11], (const float*)d_in[19]};
    const float* Alog[2] = {(const float*)d_in[12], (const float*)d_in[20]};
    const float* Dp[2]   = {(const float*)d_in[13], (const float*)d_in[21]};
    const float* gn[2]   = {(const float*)d_in[14], (const float*)d_in[22]};
    const float* Wout[2] = {(const float*)d_in[15], (const float*)d_in[23]};
    float* out = (float*)d_out;

    float *p_patches, *p_pwT, *p_t, *p_nx, *p_zx, *p_conv, *p_dt, *p_y, *p_o, *p_pool;
    cudaGetSymbolAddress((void**)&p_patches, g_patches);
    cudaGetSymbolAddress((void**)&p_pwT, g_pwT);
    cudaGetSymbolAddress((void**)&p_t, g_t);
    cudaGetSymbolAddress((void**)&p_nx, g_nx);
    cudaGetSymbolAddress((void**)&p_zx, g_zx);
    cudaGetSymbolAddress((void**)&p_conv, g_conv);
    cudaGetSymbolAddress((void**)&p_dt, g_dtv);
    cudaGetSymbolAddress((void**)&p_y, g_y);
    cudaGetSymbolAddress((void**)&p_o, g_o);
    cudaGetSymbolAddress((void**)&p_pool, g_pool);

    // stem
    k_transpose_pw<<<(kPF * kD + 255) / 256, 256>>>(patch_w, p_pwT);
    k_patchify<<<(kTOK * kPF + 255) / 256, 256>>>(x, p_patches);
    {
        dim3 g((kD + 63) / 64, (kTOK + 63) / 64, 1);
        k_sgemm_b<<<g, 256>>>(p_patches, p_pwT, p_pwT, p_t, kTOK, kD, kPF, 0, 0);
    }
    k_addpos<<<(kTOK * kD + 255) / 256, 256>>>(p_t, patch_b, pos);

    for (int i = 0; i < 2; i++) {
        k_rmsnorm256<<<kTOK, 256>>>(p_t, norms_w + i * kD, p_nx);
        // in_proj for both directions (A shared, B per dir)
        {
            dim3 g((kP + 63) / 64, (kTOK + 63) / 64, 2);
            k_sgemm_b<<<g, 256>>>(p_nx, Win[0] + i * kD * kP, Win[1] + i * kD * kP,
                                  p_zx, kTOK, kP, kD, 0, (long)kTOK * kP);
        }
        k_conv2<<<(2 * kTOK * kCDIM + 255) / 256, 256>>>(
            p_zx, cw[0] + i * kCDIM * 4, cw[1] + i * kCDIM * 4,
            cb[0] + i * kCDIM, cb[1] + i * kCDIM, p_conv);
        k_dt2<<<(2 * kTOK * kH + 255) / 256, 256>>>(
            p_zx, dtb[0] + i * kH, dtb[1] + i * kH, p_dt);
        {
            dim3 g(kB, kH, 2);
            k_scan2<<<g, 256>>>(p_conv, p_dt, Alog[0] + i * kH, Alog[1] + i * kH,
                                Dp[0] + i * kH, Dp[1] + i * kH, p_y);
        }
        k_gate_norm2<<<2 * kTOK, 256>>>(p_zx, gn[0] + i * kDIN, gn[1] + i * kDIN, p_y);
        // out_proj for both directions
        {
            dim3 g((kD + 63) / 64, (kTOK + 63) / 64, 2);
            k_sgemm_b<<<g, 256>>>(p_y, Wout[0] + i * kDIN * kD, Wout[1] + i * kDIN * kD,
                                  p_o, kTOK, kD, kDIN, (long)kTOK * kDIN, (long)kTOK * kD);
        }
        k_residual<<<(kTOK * kD + 255) / 256, 256>>>(p_t, p_o, p_o + kTOK * kD);
    }

    // final norm + pool + head
    k_rmsnorm256<<<kTOK, 256>>>(p_t, final_w, p_nx);
    k_mean<<<(kB * kD + 255) / 256, 256>>>(p_nx, p_pool);
    k_head<<<(kB * kCLS + 255) / 256, 256>>>(p_pool, head_w, head_b, out);
}

// round 4
// speedup vs baseline: 1.3116x; 1.3116x over previous
#include <cuda_runtime.h>
#include <math.h>

// ---------------- problem constants ----------------
constexpr int kB    = 16;
constexpr int kL    = 64;
constexpr int kD    = 256;
constexpr int kDIN  = 512;
constexpr int kH    = 8;
constexpr int kDH   = 64;
constexpr int kN    = 64;
constexpr int kCDIM = 640;
constexpr int kP    = 1160;
constexpr int kPF   = 768;
constexpr int kCLS  = 1000;
constexpr float kEPS = 1e-6f;
constexpr int kTOK  = kB * kL;  // 1024

// ---------------- scratch ----------------
__device__ float g_patches[kTOK*kPF];
__device__ float g_pwT[kPF*kD];
__device__ float g_t[kTOK*kD];
__device__ float g_nx[kTOK*kD];
__device__ float g_zx[2][kTOK*kP];
__device__ float g_conv[2][kTOK*kCDIM];
__device__ float g_dtv[2][kTOK*kH];
__device__ float g_y[2][kTOK*kDIN];
__device__ float g_o[2][kTOK*kD];
__device__ float g_pool[kB*kD];

// ---------------- helpers ----------------
__device__ __forceinline__ int snake_src(int l) {
    int r = l >> 3, c = l & 7;
    return r * 8 + ((r & 1) ? (7 - c) : c);
}

__device__ __forceinline__ float block_reduce_sum_256(float v) {
    __shared__ float sh[8];
    __shared__ float tot;
    int lane = threadIdx.x & 31, w = threadIdx.x >> 5;
    #pragma unroll
    for (int o = 16; o > 0; o >>= 1) v += __shfl_xor_sync(0xffffffffu, v, o);
    if (lane == 0) sh[w] = v;
    __syncthreads();
    if (w == 0) {
        float x = (lane < 8) ? sh[lane] : 0.f;
        #pragma unroll
        for (int o = 4; o > 0; o >>= 1) x += __shfl_xor_sync(0xffffffffu, x, o);
        if (lane == 0) tot = x;
    }
    __syncthreads();
    return tot;
}

__device__ __forceinline__ float siluf(float x) {
    return x / (1.f + expf(-x));
}

__device__ __forceinline__ unsigned f2tf32(float f) {
    unsigned r;
    asm("cvt.rna.tf32.f32 %0, %1;" : "=r"(r) : "f"(f));
    return r;
}

// ---------------- kernels ----------------

__global__ void k_transpose_pw(const float* __restrict__ w, float* __restrict__ wt) {
    int o = blockIdx.x * blockDim.x + threadIdx.x;
    if (o >= kPF * kD) return;
    int k = o / kD, n = o % kD;
    wt[o] = w[n * kPF + k];
}

__global__ void k_patchify(const float* __restrict__ x, float* __restrict__ p) {
    int idx = blockIdx.x * blockDim.x + threadIdx.x;
    if (idx >= kTOK * kPF) return;
    int f = idx % kPF;
    int l = (idx / kPF) % kL;
    int b = idx / (kPF * kL);
    int src = snake_src(l);
    int gr = src >> 3, gc = src & 7;
    int ch = f / 256, pr = (f / 16) % 16, pc = f % 16;
    p[idx] = x[((b * 3 + ch) * 128 + gr * 16 + pr) * 128 + gc * 16 + pc];
}

__global__ void k_addpos(float* __restrict__ t, const float* __restrict__ pb,
                         const float* __restrict__ pos) {
    int idx = blockIdx.x * blockDim.x + threadIdx.x;
    if (idx >= kTOK * kD) return;
    int d = idx % kD;
    int l = (idx / kD) % kL;
    t[idx] += pb[d] + pos[snake_src(l) * kD + d];
}

// ---- TF32 tensor-core GEMM ----
// C[z] = A[z] @ B[z].  Block tile 128x64, K-step 16. M must be a multiple of 128.
// A = Abase + z*sA (row-major MxK), B = z?B1:B0 (row-major KxN), C = Cbase + z*sC.
// Requires N % 4 == 0 (float4 loads), K % 16 == 0.
__global__ void k_gemm_tc(const float* __restrict__ Abase,
                          const float* __restrict__ B0, const float* __restrict__ B1,
                          float* __restrict__ Cbase,
                          int M, int N, int K, long sA, long sC) {
    __shared__ unsigned As[16][136];  // [k][m], stride 136 (==8 mod 32: conflict-free frags)
    __shared__ unsigned Bs[16][72];   // [k][n], stride 72  (==8 mod 32)
    int z = blockIdx.z;
    const float* A = Abase + (long)z * sA;
    const float* B = z ? B1 : B0;
    float* C = Cbase + (long)z * sC;
    int tid = threadIdx.x;            // 256
    int lane = tid & 31, warp = tid >> 5;
    int lg = lane >> 2, lt = lane & 3;
    int wm = (warp >> 1) * 32;        // 4 warps along m
    int wn = (warp & 1) * 32;         // 2 warps along n
    int m0 = blockIdx.y * 128, n0 = blockIdx.x * 64;

    float c[2][4][4];
    #pragma unroll
    for (int a = 0; a < 2; a++)
        #pragma unroll
        for (int b = 0; b < 4; b++)
            #pragma unroll
            for (int d = 0; d < 4; d++) c[a][b][d] = 0.f;

    // A-load mapping: thread -> (m row, 8 consecutive k)
    int am = tid >> 1;
    int ak = (tid & 1) * 8;
    // B-load mapping: thread -> (k row, 4 consecutive n)
    int bk = tid >> 4;
    int bn = (tid & 15) * 4;

    for (int k0 = 0; k0 < K; k0 += 16) {
        {
            const float* ap = A + (long)(m0 + am) * K + k0 + ak;
            float4 v0 = *(const float4*)(ap);
            float4 v1 = *(const float4*)(ap + 4);
            As[ak + 0][am] = f2tf32(v0.x);
            As[ak + 1][am] = f2tf32(v0.y);
            As[ak + 2][am] = f2tf32(v0.z);
            As[ak + 3][am] = f2tf32(v0.w);
            As[ak + 4][am] = f2tf32(v1.x);
            As[ak + 5][am] = f2tf32(v1.y);
            As[ak + 6][am] = f2tf32(v1.z);
            As[ak + 7][am] = f2tf32(v1.w);
        }
        {
            int gn = n0 + bn;
            float4 v;
            if (gn + 3 < N) {
                v = *(const float4*)(B + (long)(k0 + bk) * N + gn);
            } else {
                const float* bp = B + (long)(k0 + bk) * N;
                v.x = (gn + 0 < N) ? bp[gn + 0] : 0.f;
                v.y = (gn + 1 < N) ? bp[gn + 1] : 0.f;
                v.z = (gn + 2 < N) ? bp[gn + 2] : 0.f;
                v.w = (gn + 3 < N) ? bp[gn + 3] : 0.f;
            }
            Bs[bk][bn + 0] = f2tf32(v.x);
            Bs[bk][bn + 1] = f2tf32(v.y);
            Bs[bk][bn + 2] = f2tf32(v.z);
            Bs[bk][bn + 3] = f2tf32(v.w);
        }
        __syncthreads();
        #pragma unroll
        for (int k8 = 0; k8 < 16; k8 += 8) {
            unsigned afr[2][4], bfr[4][2];
            #pragma unroll
            for (int mt = 0; mt < 2; mt++) {
                int mb = wm + mt * 16;
                afr[mt][0] = As[k8 + lt][mb + lg];
                afr[mt][1] = As[k8 + lt][mb + 8 + lg];
                afr[mt][2] = As[k8 + lt + 4][mb + lg];
                afr[mt][3] = As[k8 + lt + 4][mb + 8 + lg];
            }
            #pragma unroll
            for (int nt = 0; nt < 4; nt++) {
                bfr[nt][0] = Bs[k8 + lt][wn + nt * 8 + lg];
                bfr[nt][1] = Bs[k8 + lt + 4][wn + nt * 8 + lg];
            }
            #pragma unroll
            for (int mt = 0; mt < 2; mt++)
                #pragma unroll
                for (int nt = 0; nt < 4; nt++)
                    asm volatile(
                        "mma.sync.aligned.m16n8k8.row.col.f32.tf32.tf32.f32 "
                        "{%0,%1,%2,%3}, {%4,%5,%6,%7}, {%8,%9}, {%0,%1,%2,%3};"
                        : "+f"(c[mt][nt][0]), "+f"(c[mt][nt][1]),
                          "+f"(c[mt][nt][2]), "+f"(c[mt][nt][3])
                        : "r"(afr[mt][0]), "r"(afr[mt][1]),
                          "r"(afr[mt][2]), "r"(afr[mt][3]),
                          "r"(bfr[nt][0]), "r"(bfr[nt][1]));
        }
        __syncthreads();
    }

    #pragma unroll
    for (int mt = 0; mt < 2; mt++) {
        int r0 = m0 + wm + mt * 16 + lg;
        #pragma unroll
        for (int nt = 0; nt < 4; nt++) {
            int gn = n0 + wn + nt * 8 + 2 * lt;
            if (gn < N) {
                C[(long)r0 * N + gn] = c[mt][nt][0];
                C[(long)(r0 + 8) * N + gn] = c[mt][nt][2];
                if (gn + 1 < N) {
                    C[(long)r0 * N + gn + 1] = c[mt][nt][1];
                    C[(long)(r0 + 8) * N + gn + 1] = c[mt][nt][3];
                }
            }
        }
    }
}

__global__ void k_rmsnorm256(const float* __restrict__ in, const float* __restrict__ w,
                             float* __restrict__ out) {
    int row = blockIdx.x;
    int d = threadIdx.x;
    float v = in[row * kD + d];
    float ss = block_reduce_sum_256(v * v);
    out[row * kD + d] = v * rsqrtf(ss * (1.f / kD) + kEPS) * w[d];
}

// fused: causal depthwise conv + silu (both dirs) AND softplus dt (both dirs)
__global__ void k_convdt(const float* __restrict__ zxbase,
                         const float* __restrict__ cw0, const float* __restrict__ cw1,
                         const float* __restrict__ cb0, const float* __restrict__ cb1,
                         const float* __restrict__ dtb0, const float* __restrict__ dtb1,
                         float* __restrict__ convbase, float* __restrict__ dtbase) {
    const int CONV_TOT = 2 * kTOK * kCDIM;
    const int DT_TOT = 2 * kTOK * kH;
    int idx = blockIdx.x * blockDim.x + threadIdx.x;
    if (idx < CONV_TOT) {
        int dir = idx >= kTOK * kCDIM;
        int i = idx - dir * kTOK * kCDIM;
        const float* zx = zxbase + (long)dir * kTOK * kP;
        const float* cw = dir ? cw1 : cw0;
        const float* cb = dir ? cb1 : cb0;
        int c = i % kCDIM;
        int s = (i / kCDIM) % kL;
        int b = i / (kCDIM * kL);
        float acc = cb[c];
        #pragma unroll
        for (int k = 0; k < 4; k++) {
            int sp = s - 3 + k;
            if (sp >= 0) {
                int tok = dir ? (kL - 1 - sp) : sp;
                acc += cw[c * 4 + k] * zx[(b * kL + tok) * kP + kDIN + c];
            }
        }
        convbase[idx] = siluf(acc);
    } else if (idx < CONV_TOT + DT_TOT) {
        int j = idx - CONV_TOT;
        int dir = j >= kTOK * kH;
        int i = j - dir * kTOK * kH;
        const float* zx = zxbase + (long)dir * kTOK * kP;
        const float* dtb = dir ? dtb1 : dtb0;
        int h = i % kH;
        int s = (i / kH) % kL;
        int b = i / (kH * kL);
        int tok = dir ? (kL - 1 - s) : s;
        float v = zx[(b * kL + tok) * kP + 2 * kDIN + 2 * kN + h] + dtb[h];
        dtbase[j] = (v > 20.f) ? v : log1pf(expf(v));
    }
}

// selective-scan, both dirs: grid (B, H, 2)
__global__ void k_scan2(const float* __restrict__ convbase, const float* __restrict__ dtbase,
                        const float* __restrict__ Alog0, const float* __restrict__ Alog1,
                        const float* __restrict__ Dp0, const float* __restrict__ Dp1,
                        float* __restrict__ ybase) {
    int b = blockIdx.x;
    int h = blockIdx.y;
    int dir = blockIdx.z;
    const float* conv = convbase + (long)dir * kTOK * kCDIM;
    const float* dt   = dtbase   + (long)dir * kTOK * kH;
    float* y          = ybase    + (long)dir * kTOK * kDIN;
    float a = -expf((dir ? Alog1 : Alog0)[h]);
    float dpar = (dir ? Dp1 : Dp0)[h];
    int tid = threadIdx.x;          // 256
    int p = tid >> 2;
    int nb = (tid & 3) * 16;
    float hst[16];
    #pragma unroll
    for (int j = 0; j < 16; j++) hst[j] = 0.f;
    __shared__ float sX[64], sB[64], sC[64];
    __shared__ float sdt;
    for (int s = 0; s < kL; s++) {
        const float* row = conv + (b * kL + s) * kCDIM;
        if (tid < 64) sX[tid] = row[h * kDH + tid];
        else if (tid < 128) sB[tid - 64] = row[kDIN + (tid - 64)];
        else if (tid < 192) sC[tid - 128] = row[kDIN + kN + (tid - 128)];
        else if (tid == 192) sdt = dt[(b * kL + s) * kH + h];
        __syncthreads();
        float dtv = sdt;
        float decay = expf(dtv * a);
        float xv = sX[p];
        float dtx = dtv * xv;
        float acc = 0.f;
        #pragma unroll
        for (int j = 0; j < 16; j++) {
            hst[j] = decay * hst[j] + dtx * sB[nb + j];
            acc += hst[j] * sC[nb + j];
        }
        acc += __shfl_xor_sync(0xffffffffu, acc, 1);
        acc += __shfl_xor_sync(0xffffffffu, acc, 2);
        if ((tid & 3) == 0) {
            int tok = dir ? (kL - 1 - s) : s;
            y[(b * kL + tok) * kDIN + h * kDH + p] = acc + dpar * xv;
        }
        __syncthreads();
    }
}

__global__ void k_gate_norm2(const float* __restrict__ zxbase,
                             const float* __restrict__ gn0, const float* __restrict__ gn1,
                             float* __restrict__ ybase) {
    int row = blockIdx.x;           // 0..2*TOK-1
    const float* gn = (row >= kTOK) ? gn1 : gn0;
    const float* zrow = zxbase + (long)row * kP;
    float* yrow = ybase + (long)row * kDIN;
    int t = threadIdx.x;            // 256
    float v0 = yrow[t] * siluf(zrow[t]);
    float v1 = yrow[t + 256] * siluf(zrow[t + 256]);
    float ss = block_reduce_sum_256(v0 * v0 + v1 * v1);
    float sc = rsqrtf(ss * (1.f / kDIN) + kEPS);
    yrow[t]       = v0 * sc * gn[t];
    yrow[t + 256] = v1 * sc * gn[t + 256];
}

__global__ void k_residual(float* __restrict__ t, const float* __restrict__ o0,
                           const float* __restrict__ o1) {
    int idx = blockIdx.x * blockDim.x + threadIdx.x;
    if (idx >= kTOK * kD) return;
    t[idx] += 0.5f * (o0[idx] + o1[idx]);
}

__global__ void k_mean(const float* __restrict__ nx, float* __restrict__ pool) {
    int idx = blockIdx.x * blockDim.x + threadIdx.x;
    if (idx >= kB * kD) return;
    int d = idx % kD, b = idx / kD;
    float s = 0.f;
    for (int l = 0; l < kL; l++) s += nx[(b * kL + l) * kD + d];
    pool[idx] = s * (1.f / kL);
}

__global__ void k_head(const float* __restrict__ pool, const float* __restrict__ hw,
                       const float* __restrict__ hb, float* __restrict__ out) {
    int idx = blockIdx.x * blockDim.x + threadIdx.x;
    if (idx >= kB * kCLS) return;
    int n = idx % kCLS, b = idx / kCLS;
    float s = hb[n];
    const float* prow = pool + b * kD;
    for (int k = 0; k < kD; k++) s += prow[k] * hw[k * kCLS + n];
    out[idx] = s;
}

// ---------------- launch ----------------
extern "C" void kernel_launch(void* const* d_in, const int* in_sizes, int n_in,
                              void* d_out, int out_size) {
    const float* x       = (const float*)d_in[0];
    const float* patch_w = (const float*)d_in[1];
    const float* patch_b = (const float*)d_in[2];
    const float* pos     = (const float*)d_in[3];
    const float* norms_w = (const float*)d_in[4];
    const float* final_w = (const float*)d_in[5];
    const float* head_w  = (const float*)d_in[6];
    const float* head_b  = (const float*)d_in[7];
    const float* Win[2]  = {(const float*)d_in[8],  (const float*)d_in[16]};
    const float* cw[2]   = {(const float*)d_in[9],  (const float*)d_in[17]};
    const float* cb[2]   = {(const float*)d_in[10], (const float*)d_in[18]};
    const float* dtb[2]  = {(const float*)d_in[11], (const float*)d_in[19]};
    const float* Alog[2] = {(const float*)d_in[12], (const float*)d_in[20]};
    const float* Dp[2]   = {(const float*)d_in[13], (const float*)d_in[21]};
    const float* gn[2]   = {(const float*)d_in[14], (const float*)d_in[22]};
    const float* Wout[2] = {(const float*)d_in[15], (const float*)d_in[23]};
    float* out = (float*)d_out;

    float *p_patches, *p_pwT, *p_t, *p_nx, *p_zx, *p_conv, *p_dt, *p_y, *p_o, *p_pool;
    cudaGetSymbolAddress((void**)&p_patches, g_patches);
    cudaGetSymbolAddress((void**)&p_pwT, g_pwT);
    cudaGetSymbolAddress((void**)&p_t, g_t);
    cudaGetSymbolAddress((void**)&p_nx, g_nx);
    cudaGetSymbolAddress((void**)&p_zx, g_zx);
    cudaGetSymbolAddress((void**)&p_conv, g_conv);
    cudaGetSymbolAddress((void**)&p_dt, g_dtv);
    cudaGetSymbolAddress((void**)&p_y, g_y);
    cudaGetSymbolAddress((void**)&p_o, g_o);
    cudaGetSymbolAddress((void**)&p_pool, g_pool);

    // stem
    k_transpose_pw<<<(kPF * kD + 255) / 256, 256>>>(patch_w, p_pwT);
    k_patchify<<<(kTOK * kPF + 255) / 256, 256>>>(x, p_patches);
    {
        dim3 g((kD + 63) / 64, kTOK / 128, 1);
        k_gemm_tc<<<g, 256>>>(p_patches, p_pwT, p_pwT, p_t, kTOK, kD, kPF, 0, 0);
    }
    k_addpos<<<(kTOK * kD + 255) / 256, 256>>>(p_t, patch_b, pos);

    const int CONVDT_TOT = 2 * kTOK * kCDIM + 2 * kTOK * kH;
    for (int i = 0; i < 2; i++) {
        k_rmsnorm256<<<kTOK, 256>>>(p_t, norms_w + i * kD, p_nx);
        {
            dim3 g((kP + 63) / 64, kTOK / 128, 2);
            k_gemm_tc<<<g, 256>>>(p_nx, Win[0] + i * kD * kP, Win[1] + i * kD * kP,
                                  p_zx, kTOK, kP, kD, 0, (long)kTOK * kP);
        }
        k_convdt<<<(CONVDT_TOT + 255) / 256, 256>>>(
            p_zx, cw[0] + i * kCDIM * 4, cw[1] + i * kCDIM * 4,
            cb[0] + i * kCDIM, cb[1] + i * kCDIM,
            dtb[0] + i * kH, dtb[1] + i * kH, p_conv, p_dt);
        {
            dim3 g(kB, kH, 2);
            k_scan2<<<g, 256>>>(p_conv, p_dt, Alog[0] + i * kH, Alog[1] + i * kH,
                                Dp[0] + i * kH, Dp[1] + i * kH, p_y);
        }
        k_gate_norm2<<<2 * kTOK, 256>>>(p_zx, gn[0] + i * kDIN, gn[1] + i * kDIN, p_y);
        {
            dim3 g((kD + 63) / 64, kTOK / 128, 2);
            k_gemm_tc<<<g, 256>>>(p_y, Wout[0] + i * kDIN * kD, Wout[1] + i * kDIN * kD,
                                  p_o, kTOK, kD, kDIN, (long)kTOK * kDIN, (long)kTOK * kD);
        }
        k_residual<<<(kTOK * kD + 255) / 256, 256>>>(p_t, p_o, p_o + kTOK * kD);
    }

    // final norm + pool + head
    k_rmsnorm256<<<kTOK, 256>>>(p_t, final_w, p_nx);
    k_mean<<<(kB * kD + 255) / 256, 256>>>(p_nx, p_pool);
    k_head<<<(kB * kCLS + 255) / 256, 256>>>(p_pool, head_w, head_b, out);
}

// round 5
// speedup vs baseline: 1.3883x; 1.0585x over previous
#include <cuda_runtime.h>
#include <math.h>

// ---------------- problem constants ----------------
constexpr int kB    = 16;
constexpr int kL    = 64;
constexpr int kD    = 256;
constexpr int kDIN  = 512;
constexpr int kH    = 8;
constexpr int kDH   = 64;
constexpr int kN    = 64;
constexpr int kCDIM = 640;
constexpr int kP    = 1160;
constexpr int kPF   = 768;
constexpr int kCLS  = 1000;
constexpr float kEPS = 1e-6f;
constexpr int kTOK  = kB * kL;  // 1024

// ---------------- scratch ----------------
__device__ float g_pwT[kPF*kD];
__device__ float g_t[kTOK*kD];
__device__ float g_nx[kTOK*kD];
__device__ float g_zx[2][kTOK*kP];
__device__ float g_y[2][kTOK*kDIN];
__device__ float g_o[2][kTOK*kD];

// ---------------- helpers ----------------
__device__ __forceinline__ int snake_src(int l) {
    int r = l >> 3, c = l & 7;
    return r * 8 + ((r & 1) ? (7 - c) : c);
}

__device__ __forceinline__ float block_reduce_sum_256(float v) {
    __shared__ float sh[8];
    __shared__ float tot;
    int lane = threadIdx.x & 31, w = threadIdx.x >> 5;
    #pragma unroll
    for (int o = 16; o > 0; o >>= 1) v += __shfl_xor_sync(0xffffffffu, v, o);
    if (lane == 0) sh[w] = v;
    __syncthreads();
    if (w == 0) {
        float x = (lane < 8) ? sh[lane] : 0.f;
        #pragma unroll
        for (int o = 4; o > 0; o >>= 1) x += __shfl_xor_sync(0xffffffffu, x, o);
        if (lane == 0) tot = x;
    }
    __syncthreads();
    return tot;
}

__device__ __forceinline__ float siluf(float x) {
    return x / (1.f + expf(-x));
}

__device__ __forceinline__ unsigned f2tf32(float f) {
    unsigned r;
    asm("cvt.rna.tf32.f32 %0, %1;" : "=r"(r) : "f"(f));
    return r;
}

// ---------------- kernels ----------------

__global__ void k_transpose_pw(const float* __restrict__ w, float* __restrict__ wt) {
    int o = blockIdx.x * blockDim.x + threadIdx.x;
    if (o >= kPF * kD) return;
    int k = o / kD, n = o % kD;
    wt[o] = w[n * kPF + k];
}

// ---- patch GEMM: t[m][n] = sum_f patches(m,f)*pwT[f][n] + pb[n] + pos[snake(l)][n]
// A loaded straight from the image (patchify fused); 128x64 tile, K=768.
__global__ void k_gemm_patch(const float* __restrict__ x, const float* __restrict__ Bw,
                             const float* __restrict__ pb, const float* __restrict__ pos,
                             float* __restrict__ C) {
    __shared__ unsigned As[16][136];
    __shared__ unsigned Bs[16][72];
    int tid = threadIdx.x;
    int lane = tid & 31, warp = tid >> 5;
    int lg = lane >> 2, lt = lane & 3;
    int wm = (warp >> 1) * 32;
    int wn = (warp & 1) * 32;
    int m0 = blockIdx.y * 128, n0 = blockIdx.x * 64;

    float c[2][4][4];
    #pragma unroll
    for (int a = 0; a < 2; a++)
        #pragma unroll
        for (int b = 0; b < 4; b++)
            #pragma unroll
            for (int d = 0; d < 4; d++) c[a][b][d] = 0.f;

    int am = tid >> 1;              // m within tile
    int ak = (tid & 1) * 8;         // k offset (0 or 8)
    int bk = tid >> 4;
    int bn = (tid & 15) * 4;

    // precompute A row mapping
    int m = m0 + am;
    int bimg = m >> 6, l = m & 63;
    int src = snake_src(l);
    int gr = src >> 3, gc = src & 7;

    for (int k0 = 0; k0 < kPF; k0 += 16) {
        {
            int f = k0 + ak;                 // multiple of 8
            int ch = f >> 8, rem = f & 255;
            int pr = rem >> 4, pc = rem & 15; // pc in {0,8}
            const float* ap = x + ((long)(bimg * 3 + ch) * 128 + gr * 16 + pr) * 128
                                + gc * 16 + pc;
            float4 v0 = *(const float4*)(ap);
            float4 v1 = *(const float4*)(ap + 4);
            As[ak + 0][am] = f2tf32(v0.x);
            As[ak + 1][am] = f2tf32(v0.y);
            As[ak + 2][am] = f2tf32(v0.z);
            As[ak + 3][am] = f2tf32(v0.w);
            As[ak + 4][am] = f2tf32(v1.x);
            As[ak + 5][am] = f2tf32(v1.y);
            As[ak + 6][am] = f2tf32(v1.z);
            As[ak + 7][am] = f2tf32(v1.w);
        }
        {
            float4 v = *(const float4*)(Bw + (long)(k0 + bk) * kD + n0 + bn);
            Bs[bk][bn + 0] = f2tf32(v.x);
            Bs[bk][bn + 1] = f2tf32(v.y);
            Bs[bk][bn + 2] = f2tf32(v.z);
            Bs[bk][bn + 3] = f2tf32(v.w);
        }
        __syncthreads();
        #pragma unroll
        for (int k8 = 0; k8 < 16; k8 += 8) {
            unsigned afr[2][4], bfr[4][2];
            #pragma unroll
            for (int mt = 0; mt < 2; mt++) {
                int mb = wm + mt * 16;
                afr[mt][0] = As[k8 + lt][mb + lg];
                afr[mt][1] = As[k8 + lt][mb + 8 + lg];
                afr[mt][2] = As[k8 + lt + 4][mb + lg];
                afr[mt][3] = As[k8 + lt + 4][mb + 8 + lg];
            }
            #pragma unroll
            for (int nt = 0; nt < 4; nt++) {
                bfr[nt][0] = Bs[k8 + lt][wn + nt * 8 + lg];
                bfr[nt][1] = Bs[k8 + lt + 4][wn + nt * 8 + lg];
            }
            #pragma unroll
            for (int mt = 0; mt < 2; mt++)
                #pragma unroll
                for (int nt = 0; nt < 4; nt++)
                    asm volatile(
                        "mma.sync.aligned.m16n8k8.row.col.f32.tf32.tf32.f32 "
                        "{%0,%1,%2,%3}, {%4,%5,%6,%7}, {%8,%9}, {%0,%1,%2,%3};"
                        : "+f"(c[mt][nt][0]), "+f"(c[mt][nt][1]),
                          "+f"(c[mt][nt][2]), "+f"(c[mt][nt][3])
                        : "r"(afr[mt][0]), "r"(afr[mt][1]),
                          "r"(afr[mt][2]), "r"(afr[mt][3]),
                          "r"(bfr[nt][0]), "r"(bfr[nt][1]));
        }
        __syncthreads();
    }

    #pragma unroll
    for (int mt = 0; mt < 2; mt++) {
        int r0 = m0 + wm + mt * 16 + lg;
        int l0 = r0 & 63, l8 = (r0 + 8) & 63;
        int s0 = snake_src(l0) * kD, s8 = snake_src(l8) * kD;
        #pragma unroll
        for (int nt = 0; nt < 4; nt++) {
            int gn = n0 + wn + nt * 8 + 2 * lt;
            C[(long)r0 * kD + gn]           = c[mt][nt][0] + pb[gn] + pos[s0 + gn];
            C[(long)r0 * kD + gn + 1]       = c[mt][nt][1] + pb[gn + 1] + pos[s0 + gn + 1];
            C[(long)(r0 + 8) * kD + gn]     = c[mt][nt][2] + pb[gn] + pos[s8 + gn];
            C[(long)(r0 + 8) * kD + gn + 1] = c[mt][nt][3] + pb[gn + 1] + pos[s8 + gn + 1];
        }
    }
}

// ---- general TF32 GEMM (unchanged from R4) ----
__global__ void k_gemm_tc(const float* __restrict__ Abase,
                          const float* __restrict__ B0, const float* __restrict__ B1,
                          float* __restrict__ Cbase,
                          int M, int N, int K, long sA, long sC) {
    __shared__ unsigned As[16][136];
    __shared__ unsigned Bs[16][72];
    int z = blockIdx.z;
    const float* A = Abase + (long)z * sA;
    const float* B = z ? B1 : B0;
    float* C = Cbase + (long)z * sC;
    int tid = threadIdx.x;
    int lane = tid & 31, warp = tid >> 5;
    int lg = lane >> 2, lt = lane & 3;
    int wm = (warp >> 1) * 32;
    int wn = (warp & 1) * 32;
    int m0 = blockIdx.y * 128, n0 = blockIdx.x * 64;

    float c[2][4][4];
    #pragma unroll
    for (int a = 0; a < 2; a++)
        #pragma unroll
        for (int b = 0; b < 4; b++)
            #pragma unroll
            for (int d = 0; d < 4; d++) c[a][b][d] = 0.f;

    int am = tid >> 1;
    int ak = (tid & 1) * 8;
    int bk = tid >> 4;
    int bn = (tid & 15) * 4;

    for (int k0 = 0; k0 < K; k0 += 16) {
        {
            const float* ap = A + (long)(m0 + am) * K + k0 + ak;
            float4 v0 = *(const float4*)(ap);
            float4 v1 = *(const float4*)(ap + 4);
            As[ak + 0][am] = f2tf32(v0.x);
            As[ak + 1][am] = f2tf32(v0.y);
            As[ak + 2][am] = f2tf32(v0.z);
            As[ak + 3][am] = f2tf32(v0.w);
            As[ak + 4][am] = f2tf32(v1.x);
            As[ak + 5][am] = f2tf32(v1.y);
            As[ak + 6][am] = f2tf32(v1.z);
            As[ak + 7][am] = f2tf32(v1.w);
        }
        {
            int gn = n0 + bn;
            float4 v;
            if (gn + 3 < N) {
                v = *(const float4*)(B + (long)(k0 + bk) * N + gn);
            } else {
                const float* bp = B + (long)(k0 + bk) * N;
                v.x = (gn + 0 < N) ? bp[gn + 0] : 0.f;
                v.y = (gn + 1 < N) ? bp[gn + 1] : 0.f;
                v.z = (gn + 2 < N) ? bp[gn + 2] : 0.f;
                v.w = (gn + 3 < N) ? bp[gn + 3] : 0.f;
            }
            Bs[bk][bn + 0] = f2tf32(v.x);
            Bs[bk][bn + 1] = f2tf32(v.y);
            Bs[bk][bn + 2] = f2tf32(v.z);
            Bs[bk][bn + 3] = f2tf32(v.w);
        }
        __syncthreads();
        #pragma unroll
        for (int k8 = 0; k8 < 16; k8 += 8) {
            unsigned afr[2][4], bfr[4][2];
            #pragma unroll
            for (int mt = 0; mt < 2; mt++) {
                int mb = wm + mt * 16;
                afr[mt][0] = As[k8 + lt][mb + lg];
                afr[mt][1] = As[k8 + lt][mb + 8 + lg];
                afr[mt][2] = As[k8 + lt + 4][mb + lg];
                afr[mt][3] = As[k8 + lt + 4][mb + 8 + lg];
            }
            #pragma unroll
            for (int nt = 0; nt < 4; nt++) {
                bfr[nt][0] = Bs[k8 + lt][wn + nt * 8 + lg];
                bfr[nt][1] = Bs[k8 + lt + 4][wn + nt * 8 + lg];
            }
            #pragma unroll
            for (int mt = 0; mt < 2; mt++)
                #pragma unroll
                for (int nt = 0; nt < 4; nt++)
                    asm volatile(
                        "mma.sync.aligned.m16n8k8.row.col.f32.tf32.tf32.f32 "
                        "{%0,%1,%2,%3}, {%4,%5,%6,%7}, {%8,%9}, {%0,%1,%2,%3};"
                        : "+f"(c[mt][nt][0]), "+f"(c[mt][nt][1]),
                          "+f"(c[mt][nt][2]), "+f"(c[mt][nt][3])
                        : "r"(afr[mt][0]), "r"(afr[mt][1]),
                          "r"(afr[mt][2]), "r"(afr[mt][3]),
                          "r"(bfr[nt][0]), "r"(bfr[nt][1]));
        }
        __syncthreads();
    }

    #pragma unroll
    for (int mt = 0; mt < 2; mt++) {
        int r0 = m0 + wm + mt * 16 + lg;
        #pragma unroll
        for (int nt = 0; nt < 4; nt++) {
            int gn = n0 + wn + nt * 8 + 2 * lt;
            if (gn < N) {
                C[(long)r0 * N + gn] = c[mt][nt][0];
                C[(long)(r0 + 8) * N + gn] = c[mt][nt][2];
                if (gn + 1 < N) {
                    C[(long)r0 * N + gn + 1] = c[mt][nt][1];
                    C[(long)(r0 + 8) * N + gn + 1] = c[mt][nt][3];
                }
            }
        }
    }
}

// ---- fused residual + rmsnorm: if addRes: t += 0.5*(o0+o1); nx = rmsnorm(t, w)
__global__ void k_resnorm(float* __restrict__ t, const float* __restrict__ o0,
                          const float* __restrict__ o1, const float* __restrict__ w,
                          float* __restrict__ nx, int addRes) {
    int row = blockIdx.x;
    int d = threadIdx.x;
    long i = (long)row * kD + d;
    float v = t[i];
    if (addRes) {
        v += 0.5f * (o0[i] + o1[i]);
        t[i] = v;
    }
    float ss = block_reduce_sum_256(v * v);
    nx[i] = v * rsqrtf(ss * (1.f / kD) + kEPS) * w[d];
}

// ---- fused conv + dt + selective scan; grid (B, H, 2), 256 threads
__global__ void k_scanfused(const float* __restrict__ zxbase,
                            const float* __restrict__ cw0, const float* __restrict__ cw1,
                            const float* __restrict__ cb0, const float* __restrict__ cb1,
                            const float* __restrict__ dtb0, const float* __restrict__ dtb1,
                            const float* __restrict__ Alog0, const float* __restrict__ Alog1,
                            const float* __restrict__ Dp0, const float* __restrict__ Dp1,
                            float* __restrict__ ybase) {
    int b = blockIdx.x;
    int h = blockIdx.y;
    int dir = blockIdx.z;
    const float* zx = zxbase + (long)dir * kTOK * kP;
    float* y        = ybase  + (long)dir * kTOK * kDIN;
    const float* cw  = dir ? cw1 : cw0;
    const float* cb  = dir ? cb1 : cb0;
    const float* dtb = dir ? dtb1 : dtb0;
    float a = -expf((dir ? Alog1 : Alog0)[h]);
    float dpar = (dir ? Dp1 : Dp0)[h];

    int tid = threadIdx.x;
    // conv channel assignment (xBC channel space, 0..639)
    int c = -1;
    if (tid < 64) c = h * kDH + tid;             // X slice for this head
    else if (tid < 128) c = kDIN + (tid - 64);   // B
    else if (tid < 192) c = kDIN + kN + (tid - 128); // C
    float w0 = 0, w1 = 0, w2 = 0, w3 = 0, bias = 0;
    if (c >= 0) {
        w0 = cw[c * 4 + 0]; w1 = cw[c * 4 + 1];
        w2 = cw[c * 4 + 2]; w3 = cw[c * 4 + 3];
        bias = cb[c];
    }
    float dtbv = dtb[h];

    __shared__ float sXBC[192];   // [0:64)=X, [64:128)=B, [128:192)=C
    __shared__ float sdt;

    int p = tid >> 2;
    int nb = (tid & 3) * 16;
    float hst[16];
    #pragma unroll
    for (int j = 0; j < 16; j++) hst[j] = 0.f;
    float p1 = 0.f, p2 = 0.f, p3 = 0.f;   // conv shift registers (own channel)

    // prefetch step 0
    float v = 0.f, vdt = 0.f;
    {
        int tok = dir ? (kL - 1) : 0;
        const float* row = zx + (long)(b * kL + tok) * kP;
        if (c >= 0) v = row[kDIN + c];
        if (tid == 192) vdt = row[2 * kDIN + 2 * kN + h];
    }

    for (int s = 0; s < kL; s++) {
        if (c >= 0) {
            float cv = bias + w3 * v + w2 * p1 + w1 * p2 + w0 * p3;
            p3 = p2; p2 = p1; p1 = v;
            sXBC[tid] = siluf(cv);
        }
        if (tid == 192) {
            float t = vdt + dtbv;
            sdt = (t > 20.f) ? t : log1pf(expf(t));
        }
        // prefetch next step while others finish writing
        int sn = (s + 1 < kL) ? s + 1 : s;
        int tokn = dir ? (kL - 1 - sn) : sn;
        const float* rown = zx + (long)(b * kL + tokn) * kP;
        float vn = 0.f, vdtn = 0.f;
        if (c >= 0) vn = rown[kDIN + c];
        if (tid == 192) vdtn = rown[2 * kDIN + 2 * kN + h];
        __syncthreads();

        float dtv = sdt;
        float decay = expf(dtv * a);
        float xv = sXBC[p];
        float dtx = dtv * xv;
        float acc = 0.f;
        #pragma unroll
        for (int j = 0; j < 16; j++) {
            hst[j] = decay * hst[j] + dtx * sXBC[64 + nb + j];
            acc += hst[j] * sXBC[128 + nb + j];
        }
        acc += __shfl_xor_sync(0xffffffffu, acc, 1);
        acc += __shfl_xor_sync(0xffffffffu, acc, 2);
        if ((tid & 3) == 0) {
            int tok = dir ? (kL - 1 - s) : s;
            y[(long)(b * kL + tok) * kDIN + h * kDH + p] = acc + dpar * xv;
        }
        __syncthreads();
        v = vn; vdt = vdtn;
    }
}

// ---- gate + rmsnorm over DIN, both dirs
__global__ void k_gate_norm2(const float* __restrict__ zxbase,
                             const float* __restrict__ gn0, const float* __restrict__ gn1,
                             float* __restrict__ ybase) {
    int row = blockIdx.x;           // 0..2*TOK-1
    const float* gn = (row >= kTOK) ? gn1 : gn0;
    const float* zrow = zxbase + (long)row * kP;
    float* yrow = ybase + (long)row * kDIN;
    int t = threadIdx.x;
    float v0 = yrow[t] * siluf(zrow[t]);
    float v1 = yrow[t + 256] * siluf(zrow[t + 256]);
    float ss = block_reduce_sum_256(v0 * v0 + v1 * v1);
    float sc = rsqrtf(ss * (1.f / kDIN) + kEPS);
    yrow[t]       = v0 * sc * gn[t];
    yrow[t + 256] = v1 * sc * gn[t + 256];
}

// ---- fused mean-pool + classifier head; one block per batch element
__global__ void k_meanhead(const float* __restrict__ nx, const float* __restrict__ hw,
                           const float* __restrict__ hb, float* __restrict__ out) {
    int b = blockIdx.x;
    int t = threadIdx.x;            // 256
    __shared__ float pool[kD];
    float s = 0.f;
    #pragma unroll 8
    for (int l = 0; l < kL; l++) s += nx[(long)(b * kL + l) * kD + t];
    pool[t] = s * (1.f / kL);
    __syncthreads();
    for (int n = t; n < kCLS; n += 256) {
        float acc = hb[n];
        #pragma unroll 8
        for (int k = 0; k < kD; k++) acc += pool[k] * hw[(long)k * kCLS + n];
        out[(long)b * kCLS + n] = acc;
    }
}

// ---------------- launch ----------------
extern "C" void kernel_launch(void* const* d_in, const int* in_sizes, int n_in,
                              void* d_out, int out_size) {
    const float* x       = (const float*)d_in[0];
    const float* patch_w = (const float*)d_in[1];
    const float* patch_b = (const float*)d_in[2];
    const float* pos     = (const float*)d_in[3];
    const float* norms_w = (const float*)d_in[4];
    const float* final_w = (const float*)d_in[5];
    const float* head_w  = (const float*)d_in[6];
    const float* head_b  = (const float*)d_in[7];
    const float* Win[2]  = {(const float*)d_in[8],  (const float*)d_in[16]};
    const float* cw[2]   = {(const float*)d_in[9],  (const float*)d_in[17]};
    const float* cb[2]   = {(const float*)d_in[10], (const float*)d_in[18]};
    const float* dtb[2]  = {(const float*)d_in[11], (const float*)d_in[19]};
    const float* Alog[2] = {(const float*)d_in[12], (const float*)d_in[20]};
    const float* Dp[2]   = {(const float*)d_in[13], (const float*)d_in[21]};
    const float* gn[2]   = {(const float*)d_in[14], (const float*)d_in[22]};
    const float* Wout[2] = {(const float*)d_in[15], (const float*)d_in[23]};
    float* out = (float*)d_out;

    float *p_pwT, *p_t, *p_nx, *p_zx, *p_y, *p_o;
    cudaGetSymbolAddress((void**)&p_pwT, g_pwT);
    cudaGetSymbolAddress((void**)&p_t, g_t);
    cudaGetSymbolAddress((void**)&p_nx, g_nx);
    cudaGetSymbolAddress((void**)&p_zx, g_zx);
    cudaGetSymbolAddress((void**)&p_y, g_y);
    cudaGetSymbolAddress((void**)&p_o, g_o);

    // stem: transpose weights, then fused patchify+GEMM+bias+pos
    k_transpose_pw<<<(kPF * kD + 255) / 256, 256>>>(patch_w, p_pwT);
    {
        dim3 g(kD / 64, kTOK / 128);
        k_gemm_patch<<<g, 256>>>(x, p_pwT, patch_b, pos, p_t);
    }

    for (int i = 0; i < 2; i++) {
        if (i == 0)
            k_resnorm<<<kTOK, 256>>>(p_t, p_o, p_o, norms_w, p_nx, 0);
        else
            k_resnorm<<<kTOK, 256>>>(p_t, p_o, p_o + kTOK * kD, norms_w + kD, p_nx, 1);
        {
            dim3 g((kP + 63) / 64, kTOK / 128, 2);
            k_gemm_tc<<<g, 256>>>(p_nx, Win[0] + i * kD * kP, Win[1] + i * kD * kP,
                                  p_zx, kTOK, kP, kD, 0, (long)kTOK * kP);
        }
        {
            dim3 g(kB, kH, 2);
            k_scanfused<<<g, 256>>>(p_zx,
                                    cw[0] + i * kCDIM * 4, cw[1] + i * kCDIM * 4,
                                    cb[0] + i * kCDIM, cb[1] + i * kCDIM,
                                    dtb[0] + i * kH, dtb[1] + i * kH,
                                    Alog[0] + i * kH, Alog[1] + i * kH,
                                    Dp[0] + i * kH, Dp[1] + i * kH, p_y);
        }
        k_gate_norm2<<<2 * kTOK, 256>>>(p_zx, gn[0] + i * kDIN, gn[1] + i * kDIN, p_y);
        {
            dim3 g(kD / 64, kTOK / 128, 2);
            k_gemm_tc<<<g, 256>>>(p_y, Wout[0] + i * kDIN * kD, Wout[1] + i * kDIN * kD,
                                  p_o, kTOK, kD, kDIN, (long)kTOK * kDIN, (long)kTOK * kD);
        }
    }

    // final residual + norm, then fused mean+head
    k_resnorm<<<kTOK, 256>>>(p_t, p_o, p_o + kTOK * kD, final_w, p_nx, 1);
    k_meanhead<<<kB, 256>>>(p_nx, head_w, head_b, out);
}

// round 6
// speedup vs baseline: 1.4109x; 1.0162x over previous
#include <cuda_runtime.h>
#include <math.h>

// ---------------- problem constants ----------------
constexpr int kB    = 16;
constexpr int kL    = 64;
constexpr int kD    = 256;
constexpr int kDIN  = 512;
constexpr int kH    = 8;
constexpr int kDH   = 64;
constexpr int kN    = 64;
constexpr int kCDIM = 640;
constexpr int kP    = 1160;
constexpr int kPF   = 768;
constexpr int kCLS  = 1000;
constexpr float kEPS = 1e-6f;
constexpr int kTOK  = kB * kL;  // 1024

// GEMM smem geometry (floats)
constexpr int kAStride = 36;                 // 32 + 4 pad
constexpr int kBStride = 72;                 // 64 + 8 pad
constexpr int kAStage  = 128 * kAStride;     // 4608
constexpr int kBStage  = 32 * kBStride;      // 2304
constexpr int kBBase   = 2 * kAStage;        // 9216
constexpr int kSmemFloats = 2 * kAStage + 2 * kBStage;   // 13824
constexpr int kSmemBytes  = kSmemFloats * 4;             // 55296

// ---------------- scratch ----------------
__device__ float g_t[kTOK*kD];
__device__ float g_nx[kTOK*kD];
__device__ float g_zx[2][kTOK*kP];
__device__ float g_y[2][kTOK*kDIN];
__device__ float g_o[2][kTOK*kD];

// ---------------- helpers ----------------
__device__ __forceinline__ int snake_src(int l) {
    int r = l >> 3, c = l & 7;
    return r * 8 + ((r & 1) ? (7 - c) : c);
}

__device__ __forceinline__ float block_reduce_sum_256(float v) {
    __shared__ float sh[8];
    __shared__ float tot;
    int lane = threadIdx.x & 31, w = threadIdx.x >> 5;
    #pragma unroll
    for (int o = 16; o > 0; o >>= 1) v += __shfl_xor_sync(0xffffffffu, v, o);
    if (lane == 0) sh[w] = v;
    __syncthreads();
    if (w == 0) {
        float x = (lane < 8) ? sh[lane] : 0.f;
        #pragma unroll
        for (int o = 4; o > 0; o >>= 1) x += __shfl_xor_sync(0xffffffffu, x, o);
        if (lane == 0) tot = x;
    }
    __syncthreads();
    return tot;
}

__device__ __forceinline__ float siluf(float x) {
    return x / (1.f + expf(-x));
}

__device__ __forceinline__ unsigned f2tf32(float f) {
    unsigned r;
    asm("cvt.rna.tf32.f32 %0, %1;" : "=r"(r) : "f"(f));
    return r;
}

__device__ __forceinline__ void cpa16(float* dst, const float* src) {
    unsigned d = (unsigned)__cvta_generic_to_shared(dst);
    asm volatile("cp.async.cg.shared.global [%0], [%1], 16;" :: "r"(d), "l"(src));
}

// ---------------- kernels ----------------

// ---- patch GEMM (fused patchify + transpose-B + bias + pos-embed) ----
__global__ void k_gemm_patch(const float* __restrict__ x, const float* __restrict__ Bw,
                             const float* __restrict__ pb, const float* __restrict__ pos,
                             float* __restrict__ C) {
    __shared__ unsigned As[16][136];
    __shared__ unsigned Bs[16][72];
    int tid = threadIdx.x;
    int lane = tid & 31, warp = tid >> 5;
    int lg = lane >> 2, lt = lane & 3;
    int wm = (warp >> 1) * 32;
    int wn = (warp & 1) * 32;
    int m0 = blockIdx.y * 128, n0 = blockIdx.x * 64;

    float c[2][4][4];
    #pragma unroll
    for (int a = 0; a < 2; a++)
        #pragma unroll
        for (int b = 0; b < 4; b++)
            #pragma unroll
            for (int d = 0; d < 4; d++) c[a][b][d] = 0.f;

    int am = tid >> 1;
    int ak = (tid & 1) * 8;
    int bk = tid >> 4;
    int bn = (tid & 15) * 4;

    int m = m0 + am;
    int bimg = m >> 6, l = m & 63;
    int src = snake_src(l);
    int gr = src >> 3, gc = src & 7;

    for (int k0 = 0; k0 < kPF; k0 += 16) {
        {
            int f = k0 + ak;
            int ch = f >> 8, rem = f & 255;
            int pr = rem >> 4, pc = rem & 15;
            const float* ap = x + ((long)(bimg * 3 + ch) * 128 + gr * 16 + pr) * 128
                                + gc * 16 + pc;
            float4 v0 = *(const float4*)(ap);
            float4 v1 = *(const float4*)(ap + 4);
            As[ak + 0][am] = f2tf32(v0.x);
            As[ak + 1][am] = f2tf32(v0.y);
            As[ak + 2][am] = f2tf32(v0.z);
            As[ak + 3][am] = f2tf32(v0.w);
            As[ak + 4][am] = f2tf32(v1.x);
            As[ak + 5][am] = f2tf32(v1.y);
            As[ak + 6][am] = f2tf32(v1.z);
            As[ak + 7][am] = f2tf32(v1.w);
        }
        {
            // Bs[k][n] = patch_w[n][k]  (transpose folded into load)
            #pragma unroll
            for (int j = 0; j < 4; j++)
                Bs[bk][bn + j] = f2tf32(Bw[(long)(n0 + bn + j) * kPF + k0 + bk]);
        }
        __syncthreads();
        #pragma unroll
        for (int k8 = 0; k8 < 16; k8 += 8) {
            unsigned afr[2][4], bfr[4][2];
            #pragma unroll
            for (int mt = 0; mt < 2; mt++) {
                int mb = wm + mt * 16;
                afr[mt][0] = As[k8 + lt][mb + lg];
                afr[mt][1] = As[k8 + lt][mb + 8 + lg];
                afr[mt][2] = As[k8 + lt + 4][mb + lg];
                afr[mt][3] = As[k8 + lt + 4][mb + 8 + lg];
            }
            #pragma unroll
            for (int nt = 0; nt < 4; nt++) {
                bfr[nt][0] = Bs[k8 + lt][wn + nt * 8 + lg];
                bfr[nt][1] = Bs[k8 + lt + 4][wn + nt * 8 + lg];
            }
            #pragma unroll
            for (int mt = 0; mt < 2; mt++)
                #pragma unroll
                for (int nt = 0; nt < 4; nt++)
                    asm volatile(
                        "mma.sync.aligned.m16n8k8.row.col.f32.tf32.tf32.f32 "
                        "{%0,%1,%2,%3}, {%4,%5,%6,%7}, {%8,%9}, {%0,%1,%2,%3};"
                        : "+f"(c[mt][nt][0]), "+f"(c[mt][nt][1]),
                          "+f"(c[mt][nt][2]), "+f"(c[mt][nt][3])
                        : "r"(afr[mt][0]), "r"(afr[mt][1]),
                          "r"(afr[mt][2]), "r"(afr[mt][3]),
                          "r"(bfr[nt][0]), "r"(bfr[nt][1]));
        }
        __syncthreads();
    }

    #pragma unroll
    for (int mt = 0; mt < 2; mt++) {
        int r0 = m0 + wm + mt * 16 + lg;
        int l0 = r0 & 63, l8 = (r0 + 8) & 63;
        int s0 = snake_src(l0) * kD, s8 = snake_src(l8) * kD;
        #pragma unroll
        for (int nt = 0; nt < 4; nt++) {
            int gn = n0 + wn + nt * 8 + 2 * lt;
            C[(long)r0 * kD + gn]           = c[mt][nt][0] + pb[gn] + pos[s0 + gn];
            C[(long)r0 * kD + gn + 1]       = c[mt][nt][1] + pb[gn + 1] + pos[s0 + gn + 1];
            C[(long)(r0 + 8) * kD + gn]     = c[mt][nt][2] + pb[gn] + pos[s8 + gn];
            C[(long)(r0 + 8) * kD + gn + 1] = c[mt][nt][3] + pb[gn + 1] + pos[s8 + gn + 1];
        }
    }
}

// ---- TF32 GEMM, cp.async double-buffered, K-step 32 ----
// C[z] = A[z] @ B[z]. Tile 128x64. M % 128 == 0, K % 32 == 0, N % 4 == 0.
__global__ void __launch_bounds__(256) k_gemm_tc(
        const float* __restrict__ Abase,
        const float* __restrict__ B0, const float* __restrict__ B1,
        float* __restrict__ Cbase,
        int M, int N, int K, long sA, long sC) {
    extern __shared__ float smem[];
    int z = blockIdx.z;
    const float* A = Abase + (long)z * sA;
    const float* B = z ? B1 : B0;
    float* C = Cbase + (long)z * sC;
    int tid = threadIdx.x;
    int lane = tid & 31, warp = tid >> 5;
    int lg = lane >> 2, lt = lane & 3;
    int wm = (warp >> 1) * 32;
    int wn = (warp & 1) * 32;
    int m0 = blockIdx.y * 128, n0 = blockIdx.x * 64;

    float c[2][4][4];
    #pragma unroll
    for (int a = 0; a < 2; a++)
        #pragma unroll
        for (int b = 0; b < 4; b++)
            #pragma unroll
            for (int d = 0; d < 4; d++) c[a][b][d] = 0.f;

    // load mappings
    int am = tid >> 1, ak = (tid & 1) * 16;      // A: 16 floats per thread
    int bk = tid >> 3, bn = (tid & 7) * 8;       // B: 8 floats per thread

    // zero-fill B buffers once if this block touches a partial N tile
    if (n0 + 64 > N) {
        for (int i = tid; i < 2 * kBStage; i += 256) smem[kBBase + i] = 0.f;
        __syncthreads();
    }

    int nIters = K >> 5;

    // prefetch stage 0
    {
        const float* ap = A + (long)(m0 + am) * K + ak;
        float* ad = &smem[0 * kAStage + am * kAStride + ak];
        cpa16(ad, ap); cpa16(ad + 4, ap + 4); cpa16(ad + 8, ap + 8); cpa16(ad + 12, ap + 12);
        const float* bp = B + (long)bk * N + n0 + bn;
        float* bd = &smem[kBBase + 0 * kBStage + bk * kBStride + bn];
        if (n0 + bn < N) cpa16(bd, bp);
        if (n0 + bn + 4 < N) cpa16(bd + 4, bp + 4);
        asm volatile("cp.async.commit_group;");
    }

    for (int it = 0; it < nIters; it++) {
        if (it + 1 < nIters) {
            int k0 = (it + 1) << 5;
            int st = (it + 1) & 1;
            const float* ap = A + (long)(m0 + am) * K + k0 + ak;
            float* ad = &smem[st * kAStage + am * kAStride + ak];
            cpa16(ad, ap); cpa16(ad + 4, ap + 4); cpa16(ad + 8, ap + 8); cpa16(ad + 12, ap + 12);
            const float* bp = B + (long)(k0 + bk) * N + n0 + bn;
            float* bd = &smem[kBBase + st * kBStage + bk * kBStride + bn];
            if (n0 + bn < N) cpa16(bd, bp);
            if (n0 + bn + 4 < N) cpa16(bd + 4, bp + 4);
            asm volatile("cp.async.commit_group;");
            asm volatile("cp.async.wait_group 1;");
        } else {
            asm volatile("cp.async.wait_group 0;");
        }
        __syncthreads();

        const float* Ab = &smem[(it & 1) * kAStage];
        const float* Bb = &smem[kBBase + (it & 1) * kBStage];
        #pragma unroll
        for (int k8 = 0; k8 < 32; k8 += 8) {
            unsigned afr[2][4], bfr[4][2];
            #pragma unroll
            for (int mt = 0; mt < 2; mt++) {
                int mb = wm + mt * 16;
                afr[mt][0] = f2tf32(Ab[(mb + lg) * kAStride + k8 + lt]);
                afr[mt][1] = f2tf32(Ab[(mb + 8 + lg) * kAStride + k8 + lt]);
                afr[mt][2] = f2tf32(Ab[(mb + lg) * kAStride + k8 + lt + 4]);
                afr[mt][3] = f2tf32(Ab[(mb + 8 + lg) * kAStride + k8 + lt + 4]);
            }
            #pragma unroll
            for (int nt = 0; nt < 4; nt++) {
                bfr[nt][0] = f2tf32(Bb[(k8 + lt) * kBStride + wn + nt * 8 + lg]);
                bfr[nt][1] = f2tf32(Bb[(k8 + lt + 4) * kBStride + wn + nt * 8 + lg]);
            }
            #pragma unroll
            for (int mt = 0; mt < 2; mt++)
                #pragma unroll
                for (int nt = 0; nt < 4; nt++)
                    asm volatile(
                        "mma.sync.aligned.m16n8k8.row.col.f32.tf32.tf32.f32 "
                        "{%0,%1,%2,%3}, {%4,%5,%6,%7}, {%8,%9}, {%0,%1,%2,%3};"
                        : "+f"(c[mt][nt][0]), "+f"(c[mt][nt][1]),
                          "+f"(c[mt][nt][2]), "+f"(c[mt][nt][3])
                        : "r"(afr[mt][0]), "r"(afr[mt][1]),
                          "r"(afr[mt][2]), "r"(afr[mt][3]),
                          "r"(bfr[nt][0]), "r"(bfr[nt][1]));
        }
        __syncthreads();
    }

    #pragma unroll
    for (int mt = 0; mt < 2; mt++) {
        int r0 = m0 + wm + mt * 16 + lg;
        #pragma unroll
        for (int nt = 0; nt < 4; nt++) {
            int gn = n0 + wn + nt * 8 + 2 * lt;
            if (gn < N) {
                C[(long)r0 * N + gn] = c[mt][nt][0];
                C[(long)(r0 + 8) * N + gn] = c[mt][nt][2];
                if (gn + 1 < N) {
                    C[(long)r0 * N + gn + 1] = c[mt][nt][1];
                    C[(long)(r0 + 8) * N + gn + 1] = c[mt][nt][3];
                }
            }
        }
    }
}

// ---- fused residual + rmsnorm ----
__global__ void k_resnorm(float* __restrict__ t, const float* __restrict__ o0,
                          const float* __restrict__ o1, const float* __restrict__ w,
                          float* __restrict__ nx, int addRes) {
    int row = blockIdx.x;
    int d = threadIdx.x;
    long i = (long)row * kD + d;
    float v = t[i];
    if (addRes) {
        v += 0.5f * (o0[i] + o1[i]);
        t[i] = v;
    }
    float ss = block_reduce_sum_256(v * v);
    nx[i] = v * rsqrtf(ss * (1.f / kD) + kEPS) * w[d];
}

// ---- fused conv + dt + selective scan; grid (B, H, 2), 256 threads ----
__global__ void k_scanfused(const float* __restrict__ zxbase,
                            const float* __restrict__ cw0, const float* __restrict__ cw1,
                            const float* __restrict__ cb0, const float* __restrict__ cb1,
                            const float* __restrict__ dtb0, const float* __restrict__ dtb1,
                            const float* __restrict__ Alog0, const float* __restrict__ Alog1,
                            const float* __restrict__ Dp0, const float* __restrict__ Dp1,
                            float* __restrict__ ybase) {
    int b = blockIdx.x;
    int h = blockIdx.y;
    int dir = blockIdx.z;
    const float* zx = zxbase + (long)dir * kTOK * kP;
    float* y        = ybase  + (long)dir * kTOK * kDIN;
    const float* cw  = dir ? cw1 : cw0;
    const float* cb  = dir ? cb1 : cb0;
    const float* dtb = dir ? dtb1 : dtb0;
    float a = -expf((dir ? Alog1 : Alog0)[h]);
    float dpar = (dir ? Dp1 : Dp0)[h];

    int tid = threadIdx.x;
    int c = -1;
    if (tid < 64) c = h * kDH + tid;
    else if (tid < 128) c = kDIN + (tid - 64);
    else if (tid < 192) c = kDIN + kN + (tid - 128);
    float w0 = 0, w1 = 0, w2 = 0, w3 = 0, bias = 0;
    if (c >= 0) {
        w0 = cw[c * 4 + 0]; w1 = cw[c * 4 + 1];
        w2 = cw[c * 4 + 2]; w3 = cw[c * 4 + 3];
        bias = cb[c];
    }
    float dtbv = dtb[h];

    __shared__ float sXBC[192];
    __shared__ float sdt;

    int p = tid >> 2;
    int nb = (tid & 3) * 16;
    float hst[16];
    #pragma unroll
    for (int j = 0; j < 16; j++) hst[j] = 0.f;
    float p1 = 0.f, p2 = 0.f, p3 = 0.f;

    float v = 0.f, vdt = 0.f;
    {
        int tok = dir ? (kL - 1) : 0;
        const float* row = zx + (long)(b * kL + tok) * kP;
        if (c >= 0) v = row[kDIN + c];
        if (tid == 192) vdt = row[2 * kDIN + 2 * kN + h];
    }

    for (int s = 0; s < kL; s++) {
        if (c >= 0) {
            float cv = bias + w3 * v + w2 * p1 + w1 * p2 + w0 * p3;
            p3 = p2; p2 = p1; p1 = v;
            sXBC[tid] = siluf(cv);
        }
        if (tid == 192) {
            float t = vdt + dtbv;
            sdt = (t > 20.f) ? t : log1pf(expf(t));
        }
        int sn = (s + 1 < kL) ? s + 1 : s;
        int tokn = dir ? (kL - 1 - sn) : sn;
        const float* rown = zx + (long)(b * kL + tokn) * kP;
        float vn = 0.f, vdtn = 0.f;
        if (c >= 0) vn = rown[kDIN + c];
        if (tid == 192) vdtn = rown[2 * kDIN + 2 * kN + h];
        __syncthreads();

        float dtv = sdt;
        float decay = expf(dtv * a);
        float xv = sXBC[p];
        float dtx = dtv * xv;
        float acc = 0.f;
        #pragma unroll
        for (int j = 0; j < 16; j++) {
            hst[j] = decay * hst[j] + dtx * sXBC[64 + nb + j];
            acc += hst[j] * sXBC[128 + nb + j];
        }
        acc += __shfl_xor_sync(0xffffffffu, acc, 1);
        acc += __shfl_xor_sync(0xffffffffu, acc, 2);
        if ((tid & 3) == 0) {
            int tok = dir ? (kL - 1 - s) : s;
            y[(long)(b * kL + tok) * kDIN + h * kDH + p] = acc + dpar * xv;
        }
        __syncthreads();
        v = vn; vdt = vdtn;
    }
}

// ---- gate + rmsnorm over DIN, both dirs ----
__global__ void k_gate_norm2(const float* __restrict__ zxbase,
                             const float* __restrict__ gn0, const float* __restrict__ gn1,
                             float* __restrict__ ybase) {
    int row = blockIdx.x;
    const float* gn = (row >= kTOK) ? gn1 : gn0;
    const float* zrow = zxbase + (long)row * kP;
    float* yrow = ybase + (long)row * kDIN;
    int t = threadIdx.x;
    float v0 = yrow[t] * siluf(zrow[t]);
    float v1 = yrow[t + 256] * siluf(zrow[t + 256]);
    float ss = block_reduce_sum_256(v0 * v0 + v1 * v1);
    float sc = rsqrtf(ss * (1.f / kDIN) + kEPS);
    yrow[t]       = v0 * sc * gn[t];
    yrow[t + 256] = v1 * sc * gn[t + 256];
}

// ---- fused mean-pool + classifier head ----
__global__ void k_meanhead(const float* __restrict__ nx, const float* __restrict__ hw,
                           const float* __restrict__ hb, float* __restrict__ out) {
    int b = blockIdx.x;
    int t = threadIdx.x;
    __shared__ float pool[kD];
    float s = 0.f;
    #pragma unroll 8
    for (int l = 0; l < kL; l++) s += nx[(long)(b * kL + l) * kD + t];
    pool[t] = s * (1.f / kL);
    __syncthreads();
    for (int n = t; n < kCLS; n += 256) {
        float acc = hb[n];
        #pragma unroll 8
        for (int k = 0; k < kD; k++) acc += pool[k] * hw[(long)k * kCLS + n];
        out[(long)b * kCLS + n] = acc;
    }
}

// ---------------- launch ----------------
extern "C" void kernel_launch(void* const* d_in, const int* in_sizes, int n_in,
                              void* d_out, int out_size) {
    const float* x       = (const float*)d_in[0];
    const float* patch_w = (const float*)d_in[1];
    const float* patch_b = (const float*)d_in[2];
    const float* pos     = (const float*)d_in[3];
    const float* norms_w = (const float*)d_in[4];
    const float* final_w = (const float*)d_in[5];
    const float* head_w  = (const float*)d_in[6];
    const float* head_b  = (const float*)d_in[7];
    const float* Win[2]  = {(const float*)d_in[8],  (const float*)d_in[16]};
    const float* cw[2]   = {(const float*)d_in[9],  (const float*)d_in[17]};
    const float* cb[2]   = {(const float*)d_in[10], (const float*)d_in[18]};
    const float* dtb[2]  = {(const float*)d_in[11], (const float*)d_in[19]};
    const float* Alog[2] = {(const float*)d_in[12], (const float*)d_in[20]};
    const float* Dp[2]   = {(const float*)d_in[13], (const float*)d_in[21]};
    const float* gn[2]   = {(const float*)d_in[14], (const float*)d_in[22]};
    const float* Wout[2] = {(const float*)d_in[15], (const float*)d_in[23]};
    float* out = (float*)d_out;

    float *p_t, *p_nx, *p_zx, *p_y, *p_o;
    cudaGetSymbolAddress((void**)&p_t, g_t);
    cudaGetSymbolAddress((void**)&p_nx, g_nx);
    cudaGetSymbolAddress((void**)&p_zx, g_zx);
    cudaGetSymbolAddress((void**)&p_y, g_y);
    cudaGetSymbolAddress((void**)&p_o, g_o);

    cudaFuncSetAttribute(k_gemm_tc, cudaFuncAttributeMaxDynamicSharedMemorySize, kSmemBytes);

    // stem: fused patchify + GEMM + bias + pos (transpose folded into B load)
    {
        dim3 g(kD / 64, kTOK / 128);
        k_gemm_patch<<<g, 256>>>(x, patch_w, patch_b, pos, p_t);
    }

    for (int i = 0; i < 2; i++) {
        if (i == 0)
            k_resnorm<<<kTOK, 256>>>(p_t, p_o, p_o, norms_w, p_nx, 0);
        else
            k_resnorm<<<kTOK, 256>>>(p_t, p_o, p_o + kTOK * kD, norms_w + kD, p_nx, 1);
        {
            dim3 g((kP + 63) / 64, kTOK / 128, 2);
            k_gemm_tc<<<g, 256, kSmemBytes>>>(p_nx, Win[0] + i * kD * kP, Win[1] + i * kD * kP,
                                              p_zx, kTOK, kP, kD, 0, (long)kTOK * kP);
        }
        {
            dim3 g(kB, kH, 2);
            k_scanfused<<<g, 256>>>(p_zx,
                                    cw[0] + i * kCDIM * 4, cw[1] + i * kCDIM * 4,
                                    cb[0] + i * kCDIM, cb[1] + i * kCDIM,
                                    dtb[0] + i * kH, dtb[1] + i * kH,
                                    Alog[0] + i * kH, Alog[1] + i * kH,
                                    Dp[0] + i * kH, Dp[1] + i * kH, p_y);
        }
        k_gate_norm2<<<2 * kTOK, 256>>>(p_zx, gn[0] + i * kDIN, gn[1] + i * kDIN, p_y);
        {
            dim3 g(kD / 64, kTOK / 128, 2);
            k_gemm_tc<<<g, 256, kSmemBytes>>>(p_y, Wout[0] + i * kDIN * kD, Wout[1] + i * kDIN * kD,
                                              p_o, kTOK, kD, kDIN, (long)kTOK * kDIN, (long)kTOK * kD);
        }
    }

    // final residual + norm, then fused mean+head
    k_resnorm<<<kTOK, 256>>>(p_t, p_o, p_o + kTOK * kD, final_w, p_nx, 1);
    k_meanhead<<<kB, 256>>>(p_nx, head_w, head_b, out);
}

// round 7
// speedup vs baseline: 1.9717x; 1.3975x over previous
#include <cuda_runtime.h>
#include <math.h>

// ---------------- problem constants ----------------
constexpr int kB    = 16;
constexpr int kL    = 64;
constexpr int kD    = 256;
constexpr int kDIN  = 512;
constexpr int kH    = 8;
constexpr int kDH   = 64;
constexpr int kN    = 64;
constexpr int kCDIM = 640;
constexpr int kP    = 1160;
constexpr int kPF   = 768;
constexpr int kCLS  = 1000;
constexpr float kEPS = 1e-6f;
constexpr int kTOK  = kB * kL;  // 1024

// GEMM smem geometry (floats)
constexpr int kAStride = 36;
constexpr int kBStride = 72;
constexpr int kBStage  = 32 * kBStride;      // 2304

// attn kernel smem layout (floats)
constexpr int aW   = 0;          // 64*67 (raw staging, then W)
constexpr int aX   = 4288;       // 64*68
constexpr int aBT  = 8640;       // 64*68  (B transposed: [n][s'])
constexpr int aC   = 12992;      // 64*66
constexpr int aDT  = 17216;      // 64
constexpr int aCUM = 17280;      // 64
constexpr int kAttnSmemBytes = 17344 * 4;    // 69376

// ---------------- scratch ----------------
__device__ float g_t[kTOK*kD];
__device__ float g_nx[kTOK*kD];
__device__ float g_zx[2][kTOK*kP];
__device__ float g_y[2][kTOK*kDIN];
__device__ float g_o[2][kTOK*kD];

// ---------------- helpers ----------------
__device__ __forceinline__ int snake_src(int l) {
    int r = l >> 3, c = l & 7;
    return r * 8 + ((r & 1) ? (7 - c) : c);
}

__device__ __forceinline__ float block_reduce_sum_256(float v) {
    __shared__ float sh[8];
    __shared__ float tot;
    int lane = threadIdx.x & 31, w = threadIdx.x >> 5;
    #pragma unroll
    for (int o = 16; o > 0; o >>= 1) v += __shfl_xor_sync(0xffffffffu, v, o);
    if (lane == 0) sh[w] = v;
    __syncthreads();
    if (w == 0) {
        float x = (lane < 8) ? sh[lane] : 0.f;
        #pragma unroll
        for (int o = 4; o > 0; o >>= 1) x += __shfl_xor_sync(0xffffffffu, x, o);
        if (lane == 0) tot = x;
    }
    __syncthreads();
    return tot;
}

__device__ __forceinline__ float siluf(float x) {
    return x / (1.f + expf(-x));
}

__device__ __forceinline__ unsigned f2tf32(float f) {
    unsigned r;
    asm("cvt.rna.tf32.f32 %0, %1;" : "=r"(r) : "f"(f));
    return r;
}

__device__ __forceinline__ void cpa16(float* dst, const float* src) {
    unsigned d = (unsigned)__cvta_generic_to_shared(dst);
    asm volatile("cp.async.cg.shared.global [%0], [%1], 16;" :: "r"(d), "l"(src));
}

// ---------------- kernels ----------------

// ---- patch GEMM: 64x64 tiles (fused patchify + transpose-B + bias + pos) ----
__global__ void __launch_bounds__(256) k_gemm_patch(
        const float* __restrict__ x, const float* __restrict__ Bw,
        const float* __restrict__ pb, const float* __restrict__ pos,
        float* __restrict__ C) {
    __shared__ unsigned As[16][72];
    __shared__ unsigned Bs[16][72];
    int tid = threadIdx.x;
    int lane = tid & 31, warp = tid >> 5;
    int lg = lane >> 2, lt = lane & 3;
    int wm = (warp >> 2) * 32;       // 2 m-warps
    int wn = (warp & 3) * 16;        // 4 n-warps
    int m0 = blockIdx.y * 64, n0 = blockIdx.x * 64;

    float c[2][2][4];
    #pragma unroll
    for (int a = 0; a < 2; a++)
        #pragma unroll
        for (int b = 0; b < 2; b++)
            #pragma unroll
            for (int d = 0; d < 4; d++) c[a][b][d] = 0.f;

    int am = tid >> 2;               // 0..63
    int ak = (tid & 3) * 4;          // 0,4,8,12
    int bk = tid >> 4;
    int bn = (tid & 15) * 4;

    int m = m0 + am;
    int bimg = m >> 6, l = m & 63;
    int src = snake_src(l);
    int gr = src >> 3, gc = src & 7;

    for (int k0 = 0; k0 < kPF; k0 += 16) {
        {
            int f = k0 + ak;
            int ch = f >> 8, rem = f & 255;
            int pr = rem >> 4, pc = rem & 15;   // pc in {0,4,8,12}
            const float* ap = x + ((long)(bimg * 3 + ch) * 128 + gr * 16 + pr) * 128
                                + gc * 16 + pc;
            float4 v = *(const float4*)(ap);
            As[ak + 0][am] = f2tf32(v.x);
            As[ak + 1][am] = f2tf32(v.y);
            As[ak + 2][am] = f2tf32(v.z);
            As[ak + 3][am] = f2tf32(v.w);
        }
        {
            #pragma unroll
            for (int j = 0; j < 4; j++)
                Bs[bk][bn + j] = f2tf32(Bw[(long)(n0 + bn + j) * kPF + k0 + bk]);
        }
        __syncthreads();
        #pragma unroll
        for (int k8 = 0; k8 < 16; k8 += 8) {
            unsigned afr[2][4], bfr[2][2];
            #pragma unroll
            for (int mt = 0; mt < 2; mt++) {
                int mb = wm + mt * 16;
                afr[mt][0] = As[k8 + lt][mb + lg];
                afr[mt][1] = As[k8 + lt][mb + 8 + lg];
                afr[mt][2] = As[k8 + lt + 4][mb + lg];
                afr[mt][3] = As[k8 + lt + 4][mb + 8 + lg];
            }
            #pragma unroll
            for (int nt = 0; nt < 2; nt++) {
                bfr[nt][0] = Bs[k8 + lt][wn + nt * 8 + lg];
                bfr[nt][1] = Bs[k8 + lt + 4][wn + nt * 8 + lg];
            }
            #pragma unroll
            for (int mt = 0; mt < 2; mt++)
                #pragma unroll
                for (int nt = 0; nt < 2; nt++)
                    asm volatile(
                        "mma.sync.aligned.m16n8k8.row.col.f32.tf32.tf32.f32 "
                        "{%0,%1,%2,%3}, {%4,%5,%6,%7}, {%8,%9}, {%0,%1,%2,%3};"
                        : "+f"(c[mt][nt][0]), "+f"(c[mt][nt][1]),
                          "+f"(c[mt][nt][2]), "+f"(c[mt][nt][3])
                        : "r"(afr[mt][0]), "r"(afr[mt][1]),
                          "r"(afr[mt][2]), "r"(afr[mt][3]),
                          "r"(bfr[nt][0]), "r"(bfr[nt][1]));
        }
        __syncthreads();
    }

    #pragma unroll
    for (int mt = 0; mt < 2; mt++) {
        int r0 = m0 + wm + mt * 16 + lg;
        int l0 = r0 & 63, l8 = (r0 + 8) & 63;
        int s0 = snake_src(l0) * kD, s8 = snake_src(l8) * kD;
        #pragma unroll
        for (int nt = 0; nt < 2; nt++) {
            int gn = n0 + wn + nt * 8 + 2 * lt;
            C[(long)r0 * kD + gn]           = c[mt][nt][0] + pb[gn] + pos[s0 + gn];
            C[(long)r0 * kD + gn + 1]       = c[mt][nt][1] + pb[gn + 1] + pos[s0 + gn + 1];
            C[(long)(r0 + 8) * kD + gn]     = c[mt][nt][2] + pb[gn] + pos[s8 + gn];
            C[(long)(r0 + 8) * kD + gn + 1] = c[mt][nt][3] + pb[gn + 1] + pos[s8 + gn + 1];
        }
    }
}

// ---- TF32 GEMM, cp.async double-buffered, K-step 32, templated M-tile ----
template<int MT>
__global__ void __launch_bounds__(256) k_gemm_tc(
        const float* __restrict__ Abase,
        const float* __restrict__ B0, const float* __restrict__ B1,
        float* __restrict__ Cbase,
        int M, int N, int K, long sA, long sC) {
    extern __shared__ float smem[];
    constexpr int NTF = (MT == 128) ? 4 : 2;
    constexpr int ASTAGE = MT * kAStride;
    constexpr int BBASE = 2 * ASTAGE;
    int z = blockIdx.z;
    const float* A = Abase + (long)z * sA;
    const float* B = z ? B1 : B0;
    float* C = Cbase + (long)z * sC;
    int tid = threadIdx.x;
    int lane = tid & 31, warp = tid >> 5;
    int lg = lane >> 2, lt = lane & 3;
    int wm = (MT == 128) ? (warp >> 1) * 32 : (warp >> 2) * 32;
    int wn = (MT == 128) ? (warp & 1) * 32 : (warp & 3) * 16;
    int m0 = blockIdx.y * MT, n0 = blockIdx.x * 64;

    float c[2][NTF][4];
    #pragma unroll
    for (int a = 0; a < 2; a++)
        #pragma unroll
        for (int b = 0; b < NTF; b++)
            #pragma unroll
            for (int d = 0; d < 4; d++) c[a][b][d] = 0.f;

    int am = (MT == 128) ? (tid >> 1) : (tid >> 2);
    int ak = (MT == 128) ? (tid & 1) * 16 : (tid & 3) * 8;
    int bk = tid >> 3, bn = (tid & 7) * 8;

    if (n0 + 64 > N) {
        for (int i = tid; i < 2 * kBStage; i += 256) smem[BBASE + i] = 0.f;
        __syncthreads();
    }

    int nIters = K >> 5;

    {
        const float* ap = A + (long)(m0 + am) * K + ak;
        float* ad = &smem[am * kAStride + ak];
        cpa16(ad, ap); cpa16(ad + 4, ap + 4);
        if (MT == 128) { cpa16(ad + 8, ap + 8); cpa16(ad + 12, ap + 12); }
        const float* bp = B + (long)bk * N + n0 + bn;
        float* bd = &smem[BBASE + bk * kBStride + bn];
        if (n0 + bn < N) cpa16(bd, bp);
        if (n0 + bn + 4 < N) cpa16(bd + 4, bp + 4);
        asm volatile("cp.async.commit_group;");
    }

    for (int it = 0; it < nIters; it++) {
        if (it + 1 < nIters) {
            int k0 = (it + 1) << 5;
            int st = (it + 1) & 1;
            const float* ap = A + (long)(m0 + am) * K + k0 + ak;
            float* ad = &smem[st * ASTAGE + am * kAStride + ak];
            cpa16(ad, ap); cpa16(ad + 4, ap + 4);
            if (MT == 128) { cpa16(ad + 8, ap + 8); cpa16(ad + 12, ap + 12); }
            const float* bp = B + (long)(k0 + bk) * N + n0 + bn;
            float* bd = &smem[BBASE + st * kBStage + bk * kBStride + bn];
            if (n0 + bn < N) cpa16(bd, bp);
            if (n0 + bn + 4 < N) cpa16(bd + 4, bp + 4);
            asm volatile("cp.async.commit_group;");
            asm volatile("cp.async.wait_group 1;");
        } else {
            asm volatile("cp.async.wait_group 0;");
        }
        __syncthreads();

        const float* Ab = &smem[(it & 1) * ASTAGE];
        const float* Bb = &smem[BBASE + (it & 1) * kBStage];
        #pragma unroll
        for (int k8 = 0; k8 < 32; k8 += 8) {
            unsigned afr[2][4], bfr[NTF][2];
            #pragma unroll
            for (int mt = 0; mt < 2; mt++) {
                int mb = wm + mt * 16;
                afr[mt][0] = f2tf32(Ab[(mb + lg) * kAStride + k8 + lt]);
                afr[mt][1] = f2tf32(Ab[(mb + 8 + lg) * kAStride + k8 + lt]);
                afr[mt][2] = f2tf32(Ab[(mb + lg) * kAStride + k8 + lt + 4]);
                afr[mt][3] = f2tf32(Ab[(mb + 8 + lg) * kAStride + k8 + lt + 4]);
            }
            #pragma unroll
            for (int nt = 0; nt < NTF; nt++) {
                bfr[nt][0] = f2tf32(Bb[(k8 + lt) * kBStride + wn + nt * 8 + lg]);
                bfr[nt][1] = f2tf32(Bb[(k8 + lt + 4) * kBStride + wn + nt * 8 + lg]);
            }
            #pragma unroll
            for (int mt = 0; mt < 2; mt++)
                #pragma unroll
                for (int nt = 0; nt < NTF; nt++)
                    asm volatile(
                        "mma.sync.aligned.m16n8k8.row.col.f32.tf32.tf32.f32 "
                        "{%0,%1,%2,%3}, {%4,%5,%6,%7}, {%8,%9}, {%0,%1,%2,%3};"
                        : "+f"(c[mt][nt][0]), "+f"(c[mt][nt][1]),
                          "+f"(c[mt][nt][2]), "+f"(c[mt][nt][3])
                        : "r"(afr[mt][0]), "r"(afr[mt][1]),
                          "r"(afr[mt][2]), "r"(afr[mt][3]),
                          "r"(bfr[nt][0]), "r"(bfr[nt][1]));
        }
        __syncthreads();
    }

    #pragma unroll
    for (int mt = 0; mt < 2; mt++) {
        int r0 = m0 + wm + mt * 16 + lg;
        #pragma unroll
        for (int nt = 0; nt < NTF; nt++) {
            int gn = n0 + wn + nt * 8 + 2 * lt;
            if (gn < N) {
                C[(long)r0 * N + gn] = c[mt][nt][0];
                C[(long)(r0 + 8) * N + gn] = c[mt][nt][2];
                if (gn + 1 < N) {
                    C[(long)r0 * N + gn + 1] = c[mt][nt][1];
                    C[(long)(r0 + 8) * N + gn + 1] = c[mt][nt][3];
                }
            }
        }
    }
}

// ---- fused residual + rmsnorm ----
__global__ void k_resnorm(float* __restrict__ t, const float* __restrict__ o0,
                          const float* __restrict__ o1, const float* __restrict__ w,
                          float* __restrict__ nx, int addRes) {
    int row = blockIdx.x;
    int d = threadIdx.x;
    long i = (long)row * kD + d;
    float v = t[i];
    if (addRes) {
        v += 0.5f * (o0[i] + o1[i]);
        t[i] = v;
    }
    float ss = block_reduce_sum_256(v * v);
    nx[i] = v * rsqrtf(ss * (1.f / kD) + kEPS) * w[d];
}

// ---- chunked dual-form "scan": conv + dt + decay-masked attention ----
// grid (kB, kH, 2), 256 threads.
// y[s,p] = sum_{s'<=s} exp(a*(cum[s]-cum[s'])) * dt[s'] * (C[s]·B[s']) * x[s',p] + D*x[s,p]
__global__ void __launch_bounds__(256) k_attn(
        const float* __restrict__ zxbase,
        const float* __restrict__ cw0, const float* __restrict__ cw1,
        const float* __restrict__ cb0, const float* __restrict__ cb1,
        const float* __restrict__ dtb0, const float* __restrict__ dtb1,
        const float* __restrict__ Alog0, const float* __restrict__ Alog1,
        const float* __restrict__ Dp0, const float* __restrict__ Dp1,
        float* __restrict__ ybase) {
    extern __shared__ float sm[];
    int b = blockIdx.x, h = blockIdx.y, dir = blockIdx.z;
    const float* zx = zxbase + (long)dir * kTOK * kP;
    float* y        = ybase  + (long)dir * kTOK * kDIN;
    const float* cw  = dir ? cw1 : cw0;
    const float* cb  = dir ? cb1 : cb0;
    float a = -expf((dir ? Alog1 : Alog0)[h]);
    float dpar = (dir ? Dp1 : Dp0)[h];
    float dtbv = (dir ? dtb1 : dtb0)[h];
    int tid = threadIdx.x;

    // ---- phase 0: conv + silu into sX [s][p], sBT [n][s'], sC [s][n] ----
    // segment layout in xBC space: X at h*64, B at 512, C at 576
    #pragma unroll
    for (int seg = 0; seg < 3; seg++) {
        int off = (seg == 0) ? h * kDH : (seg == 1) ? kDIN : kDIN + kN;
        // stage raw (coalesced: c fastest)
        for (int idx = tid; idx < 4096; idx += 256) {
            int s = idx >> 6, cc = idx & 63;
            int tok = dir ? (kL - 1 - s) : s;
            sm[aW + s * 67 + cc] = zx[(long)(b * kL + tok) * kP + kDIN + off + cc];
        }
        __syncthreads();
        // conv + silu
        if (seg == 1) {
            // B: s fastest, write transposed sBT[c][s]
            for (int idx = tid; idx < 4096; idx += 256) {
                int s = idx & 63, cc = idx >> 6;
                float acc = cb[off + cc];
                #pragma unroll
                for (int k = 0; k < 4; k++) {
                    int sp = s - 3 + k;
                    if (sp >= 0) acc += cw[(off + cc) * 4 + k] * sm[aW + sp * 67 + cc];
                }
                sm[aBT + cc * 68 + s] = siluf(acc);
            }
        } else {
            int dst = (seg == 0) ? aX : aC;
            int stride = (seg == 0) ? 68 : 66;
            for (int idx = tid; idx < 4096; idx += 256) {
                int s = idx >> 6, cc = idx & 63;
                float acc = cb[off + cc];
                #pragma unroll
                for (int k = 0; k < 4; k++) {
                    int sp = s - 3 + k;
                    if (sp >= 0) acc += cw[(off + cc) * 4 + k] * sm[aW + sp * 67 + cc];
                }
                sm[dst + s * stride + cc] = siluf(acc);
            }
        }
        __syncthreads();
    }

    // dt (softplus) + inclusive cumsum
    if (tid < 64) {
        int s = tid;
        int tok = dir ? (kL - 1 - s) : s;
        float v = zx[(long)(b * kL + tok) * kP + 2 * kDIN + 2 * kN + h] + dtbv;
        sm[aDT + s] = (v > 20.f) ? v : log1pf(expf(v));
    }
    __syncthreads();
    if (tid < 32) {
        float d0 = sm[aDT + 2 * tid], d1 = sm[aDT + 2 * tid + 1];
        float p = d0 + d1;
        #pragma unroll
        for (int o = 1; o < 32; o <<= 1) {
            float t = __shfl_up_sync(0xffffffffu, p, o);
            if (tid >= o) p += t;
        }
        sm[aCUM + 2 * tid] = p - d1;
        sm[aCUM + 2 * tid + 1] = p;
    }
    __syncthreads();

    // ---- phase 1: G = C @ B^T, decay mask -> W ----
    int tj = tid >> 4, ti = tid & 15;
    int s0 = tj * 4, sp0 = ti * 4;
    {
        float g[4][4];
        #pragma unroll
        for (int r = 0; r < 4; r++)
            #pragma unroll
            for (int j = 0; j < 4; j++) g[r][j] = 0.f;
        for (int n = 0; n < 64; n += 2) {
            float2 cr[4];
            #pragma unroll
            for (int r = 0; r < 4; r++)
                cr[r] = *(const float2*)&sm[aC + (s0 + r) * 66 + n];
            float4 b0 = *(const float4*)&sm[aBT + n * 68 + sp0];
            float4 b1 = *(const float4*)&sm[aBT + (n + 1) * 68 + sp0];
            #pragma unroll
            for (int r = 0; r < 4; r++) {
                g[r][0] += cr[r].x * b0.x + cr[r].y * b1.x;
                g[r][1] += cr[r].x * b0.y + cr[r].y * b1.y;
                g[r][2] += cr[r].x * b0.z + cr[r].y * b1.z;
                g[r][3] += cr[r].x * b0.w + cr[r].y * b1.w;
            }
        }
        #pragma unroll
        for (int r = 0; r < 4; r++) {
            int s = s0 + r;
            float cs = sm[aCUM + s];
            #pragma unroll
            for (int j = 0; j < 4; j++) {
                int sp = sp0 + j;
                float w = 0.f;
                if (sp <= s)
                    w = g[r][j] * __expf(a * (cs - sm[aCUM + sp])) * sm[aDT + sp];
                sm[aW + s * 67 + sp] = w;
            }
        }
    }
    __syncthreads();

    // ---- phase 2: Y = W @ X + D*x, write token-order ----
    {
        int p0 = ti * 4;
        float yv[4][4];
        #pragma unroll
        for (int r = 0; r < 4; r++)
            #pragma unroll
            for (int j = 0; j < 4; j++) yv[r][j] = 0.f;
        for (int sp = 0; sp < 64; sp++) {
            float4 xq = *(const float4*)&sm[aX + sp * 68 + p0];
            float wr[4];
            #pragma unroll
            for (int r = 0; r < 4; r++) wr[r] = sm[aW + (s0 + r) * 67 + sp];
            #pragma unroll
            for (int r = 0; r < 4; r++) {
                yv[r][0] += wr[r] * xq.x;
                yv[r][1] += wr[r] * xq.y;
                yv[r][2] += wr[r] * xq.z;
                yv[r][3] += wr[r] * xq.w;
            }
        }
        #pragma unroll
        for (int r = 0; r < 4; r++) {
            int s = s0 + r;
            float4 xq = *(const float4*)&sm[aX + s * 68 + p0];
            float4 o;
            o.x = yv[r][0] + dpar * xq.x;
            o.y = yv[r][1] + dpar * xq.y;
            o.z = yv[r][2] + dpar * xq.z;
            o.w = yv[r][3] + dpar * xq.w;
            int tok = dir ? (kL - 1 - s) : s;
            *(float4*)&y[(long)(b * kL + tok) * kDIN + h * kDH + p0] = o;
        }
    }
}

// ---- gate + rmsnorm over DIN, both dirs ----
__global__ void k_gate_norm2(const float* __restrict__ zxbase,
                             const float* __restrict__ gn0, const float* __restrict__ gn1,
                             float* __restrict__ ybase) {
    int row = blockIdx.x;
    const float* gn = (row >= kTOK) ? gn1 : gn0;
    const float* zrow = zxbase + (long)row * kP;
    float* yrow = ybase + (long)row * kDIN;
    int t = threadIdx.x;
    float v0 = yrow[t] * siluf(zrow[t]);
    float v1 = yrow[t + 256] * siluf(zrow[t + 256]);
    float ss = block_reduce_sum_256(v0 * v0 + v1 * v1);
    float sc = rsqrtf(ss * (1.f / kDIN) + kEPS);
    yrow[t]       = v0 * sc * gn[t];
    yrow[t + 256] = v1 * sc * gn[t + 256];
}

// ---- fused mean-pool + classifier head ----
__global__ void k_meanhead(const float* __restrict__ nx, const float* __restrict__ hw,
                           const float* __restrict__ hb, float* __restrict__ out) {
    int b = blockIdx.x;
    int t = threadIdx.x;
    __shared__ float pool[kD];
    float s = 0.f;
    #pragma unroll 8
    for (int l = 0; l < kL; l++) s += nx[(long)(b * kL + l) * kD + t];
    pool[t] = s * (1.f / kL);
    __syncthreads();
    for (int n = t; n < kCLS; n += 256) {
        float acc = hb[n];
        #pragma unroll 8
        for (int k = 0; k < kD; k++) acc += pool[k] * hw[(long)k * kCLS + n];
        out[(long)b * kCLS + n] = acc;
    }
}

// ---------------- launch ----------------
extern "C" void kernel_launch(void* const* d_in, const int* in_sizes, int n_in,
                              void* d_out, int out_size) {
    const float* x       = (const float*)d_in[0];
    const float* patch_w = (const float*)d_in[1];
    const float* patch_b = (const float*)d_in[2];
    const float* pos     = (const float*)d_in[3];
    const float* norms_w = (const float*)d_in[4];
    const float* final_w = (const float*)d_in[5];
    const float* head_w  = (const float*)d_in[6];
    const float* head_b  = (const float*)d_in[7];
    const float* Win[2]  = {(const float*)d_in[8],  (const float*)d_in[16]};
    const float* cw[2]   = {(const float*)d_in[9],  (const float*)d_in[17]};
    const float* cb[2]   = {(const float*)d_in[10], (const float*)d_in[18]};
    const float* dtb[2]  = {(const float*)d_in[11], (const float*)d_in[19]};
    const float* Alog[2] = {(const float*)d_in[12], (const float*)d_in[20]};
    const float* Dp[2]   = {(const float*)d_in[13], (const float*)d_in[21]};
    const float* gn[2]   = {(const float*)d_in[14], (const float*)d_in[22]};
    const float* Wout[2] = {(const float*)d_in[15], (const float*)d_in[23]};
    float* out = (float*)d_out;

    float *p_t, *p_nx, *p_zx, *p_y, *p_o;
    cudaGetSymbolAddress((void**)&p_t, g_t);
    cudaGetSymbolAddress((void**)&p_nx, g_nx);
    cudaGetSymbolAddress((void**)&p_zx, g_zx);
    cudaGetSymbolAddress((void**)&p_y, g_y);
    cudaGetSymbolAddress((void**)&p_o, g_o);

    const int smem128 = (2 * 128 * kAStride + 2 * kBStage) * 4;
    const int smem64  = (2 * 64 * kAStride + 2 * kBStage) * 4;
    cudaFuncSetAttribute(k_gemm_tc<128>, cudaFuncAttributeMaxDynamicSharedMemorySize, smem128);
    cudaFuncSetAttribute(k_gemm_tc<64>,  cudaFuncAttributeMaxDynamicSharedMemorySize, smem64);
    cudaFuncSetAttribute(k_attn, cudaFuncAttributeMaxDynamicSharedMemorySize, kAttnSmemBytes);

    // stem: fused patchify + GEMM + bias + pos
    {
        dim3 g(kD / 64, kTOK / 64);
        k_gemm_patch<<<g, 256>>>(x, patch_w, patch_b, pos, p_t);
    }

    for (int i = 0; i < 2; i++) {
        if (i == 0)
            k_resnorm<<<kTOK, 256>>>(p_t, p_o, p_o, norms_w, p_nx, 0);
        else
            k_resnorm<<<kTOK, 256>>>(p_t, p_o, p_o + kTOK * kD, norms_w + kD, p_nx, 1);
        {
            dim3 g((kP + 63) / 64, kTOK / 128, 2);
            k_gemm_tc<128><<<g, 256, smem128>>>(p_nx, Win[0] + i * kD * kP, Win[1] + i * kD * kP,
                                                p_zx, kTOK, kP, kD, 0, (long)kTOK * kP);
        }
        {
            dim3 g(kB, kH, 2);
            k_attn<<<g, 256, kAttnSmemBytes>>>(p_zx,
                                    cw[0] + i * kCDIM * 4, cw[1] + i * kCDIM * 4,
                                    cb[0] + i * kCDIM, cb[1] + i * kCDIM,
                                    dtb[0] + i * kH, dtb[1] + i * kH,
                                    Alog[0] + i * kH, Alog[1] + i * kH,
                                    Dp[0] + i * kH, Dp[1] + i * kH, p_y);
        }
        k_gate_norm2<<<2 * kTOK, 256>>>(p_zx, gn[0] + i * kDIN, gn[1] + i * kDIN, p_y);
        {
            dim3 g(kD / 64, kTOK / 64, 2);
            k_gemm_tc<64><<<g, 256, smem64>>>(p_y, Wout[0] + i * kDIN * kD, Wout[1] + i * kDIN * kD,
                                              p_o, kTOK, kD, kDIN, (long)kTOK * kDIN, (long)kTOK * kD);
        }
    }

    // final residual + norm, then fused mean+head
    k_resnorm<<<kTOK, 256>>>(p_t, p_o, p_o + kTOK * kD, final_w, p_nx, 1);
    k_meanhead<<<kB, 256>>>(p_nx, head_w, head_b, out);
}

// round 8
// speedup vs baseline: 2.2476x; 1.1400x over previous
#include <cuda_runtime.h>
#include <math.h>

// ---------------- problem constants ----------------
constexpr int kB    = 16;
constexpr int kL    = 64;
constexpr int kD    = 256;
constexpr int kDIN  = 512;
constexpr int kH    = 8;
constexpr int kDH   = 64;
constexpr int kN    = 64;
constexpr int kCDIM = 640;
constexpr int kP    = 1160;
constexpr int kPF   = 768;
constexpr int kCLS  = 1000;
constexpr float kEPS = 1e-6f;
constexpr int kTOK  = kB * kL;  // 1024

// GEMM smem geometry (floats)
constexpr int kAStride = 36;
constexpr int kBStride = 72;
constexpr int kBStage  = 32 * kBStride;      // 2304

// attn kernel smem layout (floats)
constexpr int aW   = 0;          // 64*67 (raw staging, then W)
constexpr int aX   = 4288;       // 64*68
constexpr int aBT  = 8640;       // 64*68  (B transposed: [n][s'])
constexpr int aC   = 12992;      // 64*66
constexpr int aDT  = 17216;      // 64
constexpr int aCUM = 17280;      // 64
constexpr int kAttnSmemBytes = 17344 * 4;    // 69376

// ---------------- scratch ----------------
__device__ float g_t[kTOK*kD];
__device__ float g_nx[kTOK*kD];
__device__ float g_zx[2][kTOK*kP];
__device__ float g_y[2][kTOK*kDIN];
__device__ float g_o[2][kTOK*kD];

// ---------------- helpers ----------------
__device__ __forceinline__ int snake_src(int l) {
    int r = l >> 3, c = l & 7;
    return r * 8 + ((r & 1) ? (7 - c) : c);
}

__device__ __forceinline__ float block_reduce_sum_256(float v) {
    __shared__ float sh[8];
    __shared__ float tot;
    int lane = threadIdx.x & 31, w = threadIdx.x >> 5;
    #pragma unroll
    for (int o = 16; o > 0; o >>= 1) v += __shfl_xor_sync(0xffffffffu, v, o);
    if (lane == 0) sh[w] = v;
    __syncthreads();
    if (w == 0) {
        float x = (lane < 8) ? sh[lane] : 0.f;
        #pragma unroll
        for (int o = 4; o > 0; o >>= 1) x += __shfl_xor_sync(0xffffffffu, x, o);
        if (lane == 0) tot = x;
    }
    __syncthreads();
    return tot;
}

__device__ __forceinline__ float siluf(float x) {
    return x / (1.f + expf(-x));
}

__device__ __forceinline__ unsigned f2tf32(float f) {
    unsigned r;
    asm("cvt.rna.tf32.f32 %0, %1;" : "=r"(r) : "f"(f));
    return r;
}

__device__ __forceinline__ void cpa16(float* dst, const float* src) {
    unsigned d = (unsigned)__cvta_generic_to_shared(dst);
    asm volatile("cp.async.cg.shared.global [%0], [%1], 16;" :: "r"(d), "l"(src));
}

// ---------------- kernels ----------------

// ---- patch GEMM: 64x64 tiles (fused patchify + transpose-B + bias + pos) ----
__global__ void __launch_bounds__(256) k_gemm_patch(
        const float* __restrict__ x, const float* __restrict__ Bw,
        const float* __restrict__ pb, const float* __restrict__ pos,
        float* __restrict__ C) {
    __shared__ unsigned As[16][72];
    __shared__ unsigned Bs[16][72];
    int tid = threadIdx.x;
    int lane = tid & 31, warp = tid >> 5;
    int lg = lane >> 2, lt = lane & 3;
    int wm = (warp >> 2) * 32;       // 2 m-warps
    int wn = (warp & 3) * 16;        // 4 n-warps
    int m0 = blockIdx.y * 64, n0 = blockIdx.x * 64;

    float c[2][2][4];
    #pragma unroll
    for (int a = 0; a < 2; a++)
        #pragma unroll
        for (int b = 0; b < 2; b++)
            #pragma unroll
            for (int d = 0; d < 4; d++) c[a][b][d] = 0.f;

    int am = tid >> 2;               // 0..63
    int ak = (tid & 3) * 4;          // 0,4,8,12
    int bk = tid >> 4;
    int bn = (tid & 15) * 4;

    int m = m0 + am;
    int bimg = m >> 6, l = m & 63;
    int src = snake_src(l);
    int gr = src >> 3, gc = src & 7;

    for (int k0 = 0; k0 < kPF; k0 += 16) {
        {
            int f = k0 + ak;
            int ch = f >> 8, rem = f & 255;
            int pr = rem >> 4, pc = rem & 15;   // pc in {0,4,8,12}
            const float* ap = x + ((long)(bimg * 3 + ch) * 128 + gr * 16 + pr) * 128
                                + gc * 16 + pc;
            float4 v = *(const float4*)(ap);
            As[ak + 0][am] = f2tf32(v.x);
            As[ak + 1][am] = f2tf32(v.y);
            As[ak + 2][am] = f2tf32(v.z);
            As[ak + 3][am] = f2tf32(v.w);
        }
        {
            #pragma unroll
            for (int j = 0; j < 4; j++)
                Bs[bk][bn + j] = f2tf32(Bw[(long)(n0 + bn + j) * kPF + k0 + bk]);
        }
        __syncthreads();
        #pragma unroll
        for (int k8 = 0; k8 < 16; k8 += 8) {
            unsigned afr[2][4], bfr[2][2];
            #pragma unroll
            for (int mt = 0; mt < 2; mt++) {
                int mb = wm + mt * 16;
                afr[mt][0] = As[k8 + lt][mb + lg];
                afr[mt][1] = As[k8 + lt][mb + 8 + lg];
                afr[mt][2] = As[k8 + lt + 4][mb + lg];
                afr[mt][3] = As[k8 + lt + 4][mb + 8 + lg];
            }
            #pragma unroll
            for (int nt = 0; nt < 2; nt++) {
                bfr[nt][0] = Bs[k8 + lt][wn + nt * 8 + lg];
                bfr[nt][1] = Bs[k8 + lt + 4][wn + nt * 8 + lg];
            }
            #pragma unroll
            for (int mt = 0; mt < 2; mt++)
                #pragma unroll
                for (int nt = 0; nt < 2; nt++)
                    asm volatile(
                        "mma.sync.aligned.m16n8k8.row.col.f32.tf32.tf32.f32 "
                        "{%0,%1,%2,%3}, {%4,%5,%6,%7}, {%8,%9}, {%0,%1,%2,%3};"
                        : "+f"(c[mt][nt][0]), "+f"(c[mt][nt][1]),
                          "+f"(c[mt][nt][2]), "+f"(c[mt][nt][3])
                        : "r"(afr[mt][0]), "r"(afr[mt][1]),
                          "r"(afr[mt][2]), "r"(afr[mt][3]),
                          "r"(bfr[nt][0]), "r"(bfr[nt][1]));
        }
        __syncthreads();
    }

    #pragma unroll
    for (int mt = 0; mt < 2; mt++) {
        int r0 = m0 + wm + mt * 16 + lg;
        int l0 = r0 & 63, l8 = (r0 + 8) & 63;
        int s0 = snake_src(l0) * kD, s8 = snake_src(l8) * kD;
        #pragma unroll
        for (int nt = 0; nt < 2; nt++) {
            int gn = n0 + wn + nt * 8 + 2 * lt;
            C[(long)r0 * kD + gn]           = c[mt][nt][0] + pb[gn] + pos[s0 + gn];
            C[(long)r0 * kD + gn + 1]       = c[mt][nt][1] + pb[gn + 1] + pos[s0 + gn + 1];
            C[(long)(r0 + 8) * kD + gn]     = c[mt][nt][2] + pb[gn] + pos[s8 + gn];
            C[(long)(r0 + 8) * kD + gn + 1] = c[mt][nt][3] + pb[gn + 1] + pos[s8 + gn + 1];
        }
    }
}

// ---- TF32 GEMM, cp.async double-buffered, K-step 32, templated M-tile ----
template<int MT>
__global__ void __launch_bounds__(256) k_gemm_tc(
        const float* __restrict__ Abase,
        const float* __restrict__ B0, const float* __restrict__ B1,
        float* __restrict__ Cbase,
        int M, int N, int K, long sA, long sC) {
    extern __shared__ float smem[];
    constexpr int NTF = (MT == 128) ? 4 : 2;
    constexpr int ASTAGE = MT * kAStride;
    constexpr int BBASE = 2 * ASTAGE;
    int z = blockIdx.z;
    const float* A = Abase + (long)z * sA;
    const float* B = z ? B1 : B0;
    float* C = Cbase + (long)z * sC;
    int tid = threadIdx.x;
    int lane = tid & 31, warp = tid >> 5;
    int lg = lane >> 2, lt = lane & 3;
    int wm = (MT == 128) ? (warp >> 1) * 32 : (warp >> 2) * 32;
    int wn = (MT == 128) ? (warp & 1) * 32 : (warp & 3) * 16;
    int m0 = blockIdx.y * MT, n0 = blockIdx.x * 64;

    float c[2][NTF][4];
    #pragma unroll
    for (int a = 0; a < 2; a++)
        #pragma unroll
        for (int b = 0; b < NTF; b++)
            #pragma unroll
            for (int d = 0; d < 4; d++) c[a][b][d] = 0.f;

    int am = (MT == 128) ? (tid >> 1) : (tid >> 2);
    int ak = (MT == 128) ? (tid & 1) * 16 : (tid & 3) * 8;
    int bk = tid >> 3, bn = (tid & 7) * 8;

    if (n0 + 64 > N) {
        for (int i = tid; i < 2 * kBStage; i += 256) smem[BBASE + i] = 0.f;
        __syncthreads();
    }

    int nIters = K >> 5;

    {
        const float* ap = A + (long)(m0 + am) * K + ak;
        float* ad = &smem[am * kAStride + ak];
        cpa16(ad, ap); cpa16(ad + 4, ap + 4);
        if (MT == 128) { cpa16(ad + 8, ap + 8); cpa16(ad + 12, ap + 12); }
        const float* bp = B + (long)bk * N + n0 + bn;
        float* bd = &smem[BBASE + bk * kBStride + bn];
        if (n0 + bn < N) cpa16(bd, bp);
        if (n0 + bn + 4 < N) cpa16(bd + 4, bp + 4);
        asm volatile("cp.async.commit_group;");
    }

    for (int it = 0; it < nIters; it++) {
        if (it + 1 < nIters) {
            int k0 = (it + 1) << 5;
            int st = (it + 1) & 1;
            const float* ap = A + (long)(m0 + am) * K + k0 + ak;
            float* ad = &smem[st * ASTAGE + am * kAStride + ak];
            cpa16(ad, ap); cpa16(ad + 4, ap + 4);
            if (MT == 128) { cpa16(ad + 8, ap + 8); cpa16(ad + 12, ap + 12); }
            const float* bp = B + (long)(k0 + bk) * N + n0 + bn;
            float* bd = &smem[BBASE + st * kBStage + bk * kBStride + bn];
            if (n0 + bn < N) cpa16(bd, bp);
            if (n0 + bn + 4 < N) cpa16(bd + 4, bp + 4);
            asm volatile("cp.async.commit_group;");
            asm volatile("cp.async.wait_group 1;");
        } else {
            asm volatile("cp.async.wait_group 0;");
        }
        __syncthreads();

        const float* Ab = &smem[(it & 1) * ASTAGE];
        const float* Bb = &smem[BBASE + (it & 1) * kBStage];
        #pragma unroll
        for (int k8 = 0; k8 < 32; k8 += 8) {
            unsigned afr[2][4], bfr[NTF][2];
            #pragma unroll
            for (int mt = 0; mt < 2; mt++) {
                int mb = wm + mt * 16;
                afr[mt][0] = f2tf32(Ab[(mb + lg) * kAStride + k8 + lt]);
                afr[mt][1] = f2tf32(Ab[(mb + 8 + lg) * kAStride + k8 + lt]);
                afr[mt][2] = f2tf32(Ab[(mb + lg) * kAStride + k8 + lt + 4]);
                afr[mt][3] = f2tf32(Ab[(mb + 8 + lg) * kAStride + k8 + lt + 4]);
            }
            #pragma unroll
            for (int nt = 0; nt < NTF; nt++) {
                bfr[nt][0] = f2tf32(Bb[(k8 + lt) * kBStride + wn + nt * 8 + lg]);
                bfr[nt][1] = f2tf32(Bb[(k8 + lt + 4) * kBStride + wn + nt * 8 + lg]);
            }
            #pragma unroll
            for (int mt = 0; mt < 2; mt++)
                #pragma unroll
                for (int nt = 0; nt < NTF; nt++)
                    asm volatile(
                        "mma.sync.aligned.m16n8k8.row.col.f32.tf32.tf32.f32 "
                        "{%0,%1,%2,%3}, {%4,%5,%6,%7}, {%8,%9}, {%0,%1,%2,%3};"
                        : "+f"(c[mt][nt][0]), "+f"(c[mt][nt][1]),
                          "+f"(c[mt][nt][2]), "+f"(c[mt][nt][3])
                        : "r"(afr[mt][0]), "r"(afr[mt][1]),
                          "r"(afr[mt][2]), "r"(afr[mt][3]),
                          "r"(bfr[nt][0]), "r"(bfr[nt][1]));
        }
        __syncthreads();
    }

    #pragma unroll
    for (int mt = 0; mt < 2; mt++) {
        int r0 = m0 + wm + mt * 16 + lg;
        #pragma unroll
        for (int nt = 0; nt < NTF; nt++) {
            int gn = n0 + wn + nt * 8 + 2 * lt;
            if (gn < N) {
                C[(long)r0 * N + gn] = c[mt][nt][0];
                C[(long)(r0 + 8) * N + gn] = c[mt][nt][2];
                if (gn + 1 < N) {
                    C[(long)r0 * N + gn + 1] = c[mt][nt][1];
                    C[(long)(r0 + 8) * N + gn + 1] = c[mt][nt][3];
                }
            }
        }
    }
}

// ---- fused residual + rmsnorm ----
__global__ void k_resnorm(float* __restrict__ t, const float* __restrict__ o0,
                          const float* __restrict__ o1, const float* __restrict__ w,
                          float* __restrict__ nx, int addRes) {
    int row = blockIdx.x;
    int d = threadIdx.x;
    long i = (long)row * kD + d;
    float v = t[i];
    if (addRes) {
        v += 0.5f * (o0[i] + o1[i]);
        t[i] = v;
    }
    float ss = block_reduce_sum_256(v * v);
    nx[i] = v * rsqrtf(ss * (1.f / kD) + kEPS) * w[d];
}

// ---- chunked dual-form "scan": conv + dt + decay-masked attention ----
// grid (kB, kH, 2), 512 threads.
__global__ void __launch_bounds__(512) k_attn(
        const float* __restrict__ zxbase,
        const float* __restrict__ cw0, const float* __restrict__ cw1,
        const float* __restrict__ cb0, const float* __restrict__ cb1,
        const float* __restrict__ dtb0, const float* __restrict__ dtb1,
        const float* __restrict__ Alog0, const float* __restrict__ Alog1,
        const float* __restrict__ Dp0, const float* __restrict__ Dp1,
        float* __restrict__ ybase) {
    extern __shared__ float sm[];
    int b = blockIdx.x, h = blockIdx.y, dir = blockIdx.z;
    const float* zx = zxbase + (long)dir * kTOK * kP;
    float* y        = ybase  + (long)dir * kTOK * kDIN;
    const float* cw  = dir ? cw1 : cw0;
    const float* cb  = dir ? cb1 : cb0;
    float a = -expf((dir ? Alog1 : Alog0)[h]);
    float dpar = (dir ? Dp1 : Dp0)[h];
    float dtbv = (dir ? dtb1 : dtb0)[h];
    int tid = threadIdx.x;
    int nthr = blockDim.x;   // 512

    // ---- phase 0: conv + silu into sX [s][p], sBT [n][s'], sC [s][n] ----
    #pragma unroll
    for (int seg = 0; seg < 3; seg++) {
        int off = (seg == 0) ? h * kDH : (seg == 1) ? kDIN : kDIN + kN;
        for (int idx = tid; idx < 4096; idx += nthr) {
            int s = idx >> 6, cc = idx & 63;
            int tok = dir ? (kL - 1 - s) : s;
            sm[aW + s * 67 + cc] = zx[(long)(b * kL + tok) * kP + kDIN + off + cc];
        }
        __syncthreads();
        if (seg == 1) {
            for (int idx = tid; idx < 4096; idx += nthr) {
                int s = idx & 63, cc = idx >> 6;
                float acc = cb[off + cc];
                #pragma unroll
                for (int k = 0; k < 4; k++) {
                    int sp = s - 3 + k;
                    if (sp >= 0) acc += cw[(off + cc) * 4 + k] * sm[aW + sp * 67 + cc];
                }
                sm[aBT + cc * 68 + s] = siluf(acc);
            }
        } else {
            int dst = (seg == 0) ? aX : aC;
            int stride = (seg == 0) ? 68 : 66;
            for (int idx = tid; idx < 4096; idx += nthr) {
                int s = idx >> 6, cc = idx & 63;
                float acc = cb[off + cc];
                #pragma unroll
                for (int k = 0; k < 4; k++) {
                    int sp = s - 3 + k;
                    if (sp >= 0) acc += cw[(off + cc) * 4 + k] * sm[aW + sp * 67 + cc];
                }
                sm[dst + s * stride + cc] = siluf(acc);
            }
        }
        __syncthreads();
    }

    // dt (softplus) + inclusive cumsum
    if (tid < 64) {
        int s = tid;
        int tok = dir ? (kL - 1 - s) : s;
        float v = zx[(long)(b * kL + tok) * kP + 2 * kDIN + 2 * kN + h] + dtbv;
        sm[aDT + s] = (v > 20.f) ? v : log1pf(expf(v));
    }
    __syncthreads();
    if (tid < 32) {
        float d0 = sm[aDT + 2 * tid], d1 = sm[aDT + 2 * tid + 1];
        float p = d0 + d1;
        #pragma unroll
        for (int o = 1; o < 32; o <<= 1) {
            float t = __shfl_up_sync(0xffffffffu, p, o);
            if (tid >= o) p += t;
        }
        sm[aCUM + 2 * tid] = p - d1;
        sm[aCUM + 2 * tid + 1] = p;
    }
    __syncthreads();

    // ---- phase 1: G = C @ B^T, decay mask -> W ----
    // 512 threads: each does 2 rows x 4 cols
    int rg = tid >> 4;               // 0..31
    int ti = tid & 15;               // 0..15
    int s0 = rg * 2, sp0 = ti * 4;
    {
        float g[2][4];
        #pragma unroll
        for (int r = 0; r < 2; r++)
            #pragma unroll
            for (int j = 0; j < 4; j++) g[r][j] = 0.f;
        for (int n = 0; n < 64; n += 2) {
            float2 cr[2];
            #pragma unroll
            for (int r = 0; r < 2; r++)
                cr[r] = *(const float2*)&sm[aC + (s0 + r) * 66 + n];
            float4 b0 = *(const float4*)&sm[aBT + n * 68 + sp0];
            float4 b1 = *(const float4*)&sm[aBT + (n + 1) * 68 + sp0];
            #pragma unroll
            for (int r = 0; r < 2; r++) {
                g[r][0] += cr[r].x * b0.x + cr[r].y * b1.x;
                g[r][1] += cr[r].x * b0.y + cr[r].y * b1.y;
                g[r][2] += cr[r].x * b0.z + cr[r].y * b1.z;
                g[r][3] += cr[r].x * b0.w + cr[r].y * b1.w;
            }
        }
        #pragma unroll
        for (int r = 0; r < 2; r++) {
            int s = s0 + r;
            float cs = sm[aCUM + s];
            #pragma unroll
            for (int j = 0; j < 4; j++) {
                int sp = sp0 + j;
                float w = 0.f;
                if (sp <= s)
                    w = g[r][j] * __expf(a * (cs - sm[aCUM + sp])) * sm[aDT + sp];
                sm[aW + s * 67 + sp] = w;
            }
        }
    }
    __syncthreads();

    // ---- phase 2: Y = W @ X + D*x, write token-order ----
    {
        int p0 = ti * 4;
        float yv[2][4];
        #pragma unroll
        for (int r = 0; r < 2; r++)
            #pragma unroll
            for (int j = 0; j < 4; j++) yv[r][j] = 0.f;
        for (int sp = 0; sp < 64; sp++) {
            float4 xq = *(const float4*)&sm[aX + sp * 68 + p0];
            float wr[2];
            #pragma unroll
            for (int r = 0; r < 2; r++) wr[r] = sm[aW + (s0 + r) * 67 + sp];
            #pragma unroll
            for (int r = 0; r < 2; r++) {
                yv[r][0] += wr[r] * xq.x;
                yv[r][1] += wr[r] * xq.y;
                yv[r][2] += wr[r] * xq.z;
                yv[r][3] += wr[r] * xq.w;
            }
        }
        #pragma unroll
        for (int r = 0; r < 2; r++) {
            int s = s0 + r;
            float4 xq = *(const float4*)&sm[aX + s * 68 + p0];
            float4 o;
            o.x = yv[r][0] + dpar * xq.x;
            o.y = yv[r][1] + dpar * xq.y;
            o.z = yv[r][2] + dpar * xq.z;
            o.w = yv[r][3] + dpar * xq.w;
            int tok = dir ? (kL - 1 - s) : s;
            *(float4*)&y[(long)(b * kL + tok) * kDIN + h * kDH + p0] = o;
        }
    }
}

// ---- gate + rmsnorm over DIN, both dirs ----
__global__ void k_gate_norm2(const float* __restrict__ zxbase,
                             const float* __restrict__ gn0, const float* __restrict__ gn1,
                             float* __restrict__ ybase) {
    int row = blockIdx.x;
    const float* gn = (row >= kTOK) ? gn1 : gn0;
    const float* zrow = zxbase + (long)row * kP;
    float* yrow = ybase + (long)row * kDIN;
    int t = threadIdx.x;
    float v0 = yrow[t] * siluf(zrow[t]);
    float v1 = yrow[t + 256] * siluf(zrow[t + 256]);
    float ss = block_reduce_sum_256(v0 * v0 + v1 * v1);
    float sc = rsqrtf(ss * (1.f / kDIN) + kEPS);
    yrow[t]       = v0 * sc * gn[t];
    yrow[t + 256] = v1 * sc * gn[t + 256];
}

// ---- fused mean-pool + classifier head; grid (kB, 5), 200 classes/block ----
__global__ void k_meanhead(const float* __restrict__ nx, const float* __restrict__ hw,
                           const float* __restrict__ hb, float* __restrict__ out) {
    int b = blockIdx.x;
    int c0 = blockIdx.y * 200;
    int t = threadIdx.x;
    __shared__ float pool[kD];
    float s = 0.f;
    #pragma unroll 8
    for (int l = 0; l < kL; l++) s += nx[(long)(b * kL + l) * kD + t];
    pool[t] = s * (1.f / kL);
    __syncthreads();
    for (int n = c0 + t; n < c0 + 200 && n < kCLS; n += 256) {
        float acc = hb[n];
        #pragma unroll 8
        for (int k = 0; k < kD; k++) acc += pool[k] * hw[(long)k * kCLS + n];
        out[(long)b * kCLS + n] = acc;
    }
}

// ---------------- launch ----------------
extern "C" void kernel_launch(void* const* d_in, const int* in_sizes, int n_in,
                              void* d_out, int out_size) {
    const float* x       = (const float*)d_in[0];
    const float* patch_w = (const float*)d_in[1];
    const float* patch_b = (const float*)d_in[2];
    const float* pos     = (const float*)d_in[3];
    const float* norms_w = (const float*)d_in[4];
    const float* final_w = (const float*)d_in[5];
    const float* head_w  = (const float*)d_in[6];
    const float* head_b  = (const float*)d_in[7];
    const float* Win[2]  = {(const float*)d_in[8],  (const float*)d_in[16]};
    const float* cw[2]   = {(const float*)d_in[9],  (const float*)d_in[17]};
    const float* cb[2]   = {(const float*)d_in[10], (const float*)d_in[18]};
    const float* dtb[2]  = {(const float*)d_in[11], (const float*)d_in[19]};
    const float* Alog[2] = {(const float*)d_in[12], (const float*)d_in[20]};
    const float* Dp[2]   = {(const float*)d_in[13], (const float*)d_in[21]};
    const float* gn[2]   = {(const float*)d_in[14], (const float*)d_in[22]};
    const float* Wout[2] = {(const float*)d_in[15], (const float*)d_in[23]};
    float* out = (float*)d_out;

    float *p_t, *p_nx, *p_zx, *p_y, *p_o;
    cudaGetSymbolAddress((void**)&p_t, g_t);
    cudaGetSymbolAddress((void**)&p_nx, g_nx);
    cudaGetSymbolAddress((void**)&p_zx, g_zx);
    cudaGetSymbolAddress((void**)&p_y, g_y);
    cudaGetSymbolAddress((void**)&p_o, g_o);

    const int smem64  = (2 * 64 * kAStride + 2 * kBStage) * 4;
    cudaFuncSetAttribute(k_gemm_tc<64>,  cudaFuncAttributeMaxDynamicSharedMemorySize, smem64);
    cudaFuncSetAttribute(k_attn, cudaFuncAttributeMaxDynamicSharedMemorySize, kAttnSmemBytes);

    // stem: fused patchify + GEMM + bias + pos
    {
        dim3 g(kD / 64, kTOK / 64);
        k_gemm_patch<<<g, 256>>>(x, patch_w, patch_b, pos, p_t);
    }

    for (int i = 0; i < 2; i++) {
        if (i == 0)
            k_resnorm<<<kTOK, 256>>>(p_t, p_o, p_o, norms_w, p_nx, 0);
        else
            k_resnorm<<<kTOK, 256>>>(p_t, p_o, p_o + kTOK * kD, norms_w + kD, p_nx, 1);
        {
            dim3 g((kP + 63) / 64, kTOK / 64, 2);
            k_gemm_tc<64><<<g, 256, smem64>>>(p_nx, Win[0] + i * kD * kP, Win[1] + i * kD * kP,
                                              p_zx, kTOK, kP, kD, 0, (long)kTOK * kP);
        }
        {
            dim3 g(kB, kH, 2);
            k_attn<<<g, 512, kAttnSmemBytes>>>(p_zx,
                                    cw[0] + i * kCDIM * 4, cw[1] + i * kCDIM * 4,
                                    cb[0] + i * kCDIM, cb[1] + i * kCDIM,
                                    dtb[0] + i * kH, dtb[1] + i * kH,
                                    Alog[0] + i * kH, Alog[1] + i * kH,
                                    Dp[0] + i * kH, Dp[1] + i * kH, p_y);
        }
        k_gate_norm2<<<2 * kTOK, 256>>>(p_zx, gn[0] + i * kDIN, gn[1] + i * kDIN, p_y);
        {
            dim3 g(kD / 64, kTOK / 64, 2);
            k_gemm_tc<64><<<g, 256, smem64>>>(p_y, Wout[0] + i * kDIN * kD, Wout[1] + i * kDIN * kD,
                                              p_o, kTOK, kD, kDIN, (long)kTOK * kDIN, (long)kTOK * kD);
        }
    }

    // final residual + norm, then fused mean+head
    k_resnorm<<<kTOK, 256>>>(p_t, p_o, p_o + kTOK * kD, final_w, p_nx, 1);
    k_meanhead<<<dim3(kB, 5), 256>>>(p_nx, head_w, head_b, out);
}